// round 5
// baseline (speedup 1.0000x reference)
#include <cuda_runtime.h>
#include <cuda_bf16.h>
#include <cstdint>

#define NN 100000
#define EE 1600000
#define CIN 128
#define CC 64
#define NB_SCAN 196   // ceil(NN/512)

// ---------------- scratch (device globals; no allocation allowed) ----------
__device__ float g_h [NN * CC];
__device__ float g_t1[NN * CC];
__device__ float g_t2[NN * CC];
__device__ float g_t3[NN * CC];
__device__ int   g_src[EE];
__device__ int   g_dst[EE];
__device__ int2  g_edge[EE];      // sorted-by-dst: {src, __float_as_int(val)}
__device__ int   g_rowptr[NN + 1];
__device__ int   g_cnt[NN];       // histogram, then running scatter offsets
__device__ int   g_bsum[NB_SCAN];
__device__ int   g_bsumex[NB_SCAN];
__device__ int   g_flag[1];

// ---------------- index width detection ------------------------------------
// int64 indices with values < 2^31: every odd 32-bit word is 0. 64 random
// int32 indices in [0,1e5) being all zero is impossible.
__global__ void detect_kernel(const unsigned int* p) {
    if (threadIdx.x == 0 && blockIdx.x == 0) {
        int is64 = 1;
        for (int i = 1; i < 128; i += 2)
            if (p[i] != 0u) { is64 = 0; break; }
        g_flag[0] = is64;
    }
}

__global__ void zero_cnt_kernel() {
    int i = blockIdx.x * blockDim.x + threadIdx.x;
    if (i < NN) g_cnt[i] = 0;
}

__global__ void convert_hist_kernel(const void* srcp, const void* dstp) {
    int e = blockIdx.x * blockDim.x + threadIdx.x;
    if (e >= EE) return;
    int s, d;
    if (g_flag[0]) {
        s = (int)((const long long*)srcp)[e];
        d = (int)((const long long*)dstp)[e];
    } else {
        s = ((const int*)srcp)[e];
        d = ((const int*)dstp)[e];
    }
    g_src[e] = s;
    g_dst[e] = d;
    atomicAdd(&g_cnt[d], 1);
}

// ---------------- 2-level exclusive scan over g_cnt ------------------------
__global__ void scan_block_kernel() {   // 512 threads per block
    __shared__ int s[512];
    int tid = threadIdx.x;
    int i = blockIdx.x * 512 + tid;
    int v = (i < NN) ? g_cnt[i] : 0;
    s[tid] = v;
    __syncthreads();
#pragma unroll
    for (int off = 1; off < 512; off <<= 1) {
        int t = (tid >= off) ? s[tid - off] : 0;
        __syncthreads();
        s[tid] += t;
        __syncthreads();
    }
    if (i < NN) g_rowptr[i] = s[tid] - v;
    if (tid == 511) g_bsum[blockIdx.x] = s[511];
}

__global__ void scan_bsum_kernel() {    // single block, 256 threads
    __shared__ int s[256];
    int tid = threadIdx.x;
    int v = (tid < NB_SCAN) ? g_bsum[tid] : 0;
    s[tid] = v;
    __syncthreads();
#pragma unroll
    for (int off = 1; off < 256; off <<= 1) {
        int t = (tid >= off) ? s[tid - off] : 0;
        __syncthreads();
        s[tid] += t;
        __syncthreads();
    }
    if (tid < NB_SCAN) g_bsumex[tid] = s[tid] - v;
}

__global__ void add_offsets_kernel() {
    int i = blockIdx.x * blockDim.x + threadIdx.x;
    if (i < NN) {
        int r = g_rowptr[i] + g_bsumex[i >> 9];
        g_rowptr[i] = r;
        g_cnt[i] = r;
    }
    if (i == 0) g_rowptr[NN] = EE;
}

__global__ void scatter_kernel(const float* __restrict__ vals) {
    int e = blockIdx.x * blockDim.x + threadIdx.x;
    if (e >= EE) return;
    int d = g_dst[e];
    int pos = atomicAdd(&g_cnt[d], 1);
    g_edge[pos] = make_int2(g_src[e], __float_as_int(vals[e]));
}

// ---------------- input GEMM: h = relu(x @ W_in + b_in) ---------------------
__global__ void gemm_in_kernel(const float* __restrict__ x,
                               const float* __restrict__ Win,
                               const float* __restrict__ bin) {
    __shared__ float2 Ws[CIN * 32];
    __shared__ float bs[CC];
    for (int i = threadIdx.x; i < CIN * 32; i += blockDim.x) {
        int k = i >> 5, l = i & 31;
        Ws[i] = make_float2(Win[k * CC + l], Win[k * CC + l + 32]);
    }
    if (threadIdx.x < CC) bs[threadIdx.x] = bin[threadIdx.x];
    __syncthreads();

    int lane = threadIdx.x & 31;
    int gw = (blockIdx.x * blockDim.x + threadIdx.x) >> 5;
    int nw = (gridDim.x * blockDim.x) >> 5;
    const int NG = NN / 4;   // 25000, exact

    for (int g = gw; g < NG; g += nw) {
        int n0 = g * 4;
        const float4* xr0 = (const float4*)(x + (size_t)(n0 + 0) * CIN);
        const float4* xr1 = (const float4*)(x + (size_t)(n0 + 1) * CIN);
        const float4* xr2 = (const float4*)(x + (size_t)(n0 + 2) * CIN);
        const float4* xr3 = (const float4*)(x + (size_t)(n0 + 3) * CIN);
        float b0 = bs[lane], b1 = bs[lane + 32];
        float a00 = b0, a01 = b1, a10 = b0, a11 = b1;
        float a20 = b0, a21 = b1, a30 = b0, a31 = b1;
#pragma unroll 4
        for (int k4 = 0; k4 < CIN / 4; k4++) {
            float xa[4], xb[4], xc[4], xd[4];
            *(float4*)xa = __ldg(&xr0[k4]);
            *(float4*)xb = __ldg(&xr1[k4]);
            *(float4*)xc = __ldg(&xr2[k4]);
            *(float4*)xd = __ldg(&xr3[k4]);
#pragma unroll
            for (int kk = 0; kk < 4; kk++) {
                float2 w = Ws[(k4 * 4 + kk) * 32 + lane];
                a00 = fmaf(xa[kk], w.x, a00); a01 = fmaf(xa[kk], w.y, a01);
                a10 = fmaf(xb[kk], w.x, a10); a11 = fmaf(xb[kk], w.y, a11);
                a20 = fmaf(xc[kk], w.x, a20); a21 = fmaf(xc[kk], w.y, a21);
                a30 = fmaf(xd[kk], w.x, a30); a31 = fmaf(xd[kk], w.y, a31);
            }
        }
        g_h[(size_t)(n0 + 0) * CC + lane]      = fmaxf(a00, 0.f);
        g_h[(size_t)(n0 + 0) * CC + lane + 32] = fmaxf(a01, 0.f);
        g_h[(size_t)(n0 + 1) * CC + lane]      = fmaxf(a10, 0.f);
        g_h[(size_t)(n0 + 1) * CC + lane + 32] = fmaxf(a11, 0.f);
        g_h[(size_t)(n0 + 2) * CC + lane]      = fmaxf(a20, 0.f);
        g_h[(size_t)(n0 + 2) * CC + lane + 32] = fmaxf(a21, 0.f);
        g_h[(size_t)(n0 + 3) * CC + lane]      = fmaxf(a30, 0.f);
        g_h[(size_t)(n0 + 3) * CC + lane + 32] = fmaxf(a31, 0.f);
    }
}

// ---------------- CSR SpMM (no atomics, float2 lanes) -----------------------
// One warp per dst row; lane owns channels (2*lane, 2*lane+1).
template <int S>
__global__ void spmm_csr_kernel() {
    const float2* __restrict__ in =
        (const float2*)((S == 0) ? g_h : (S == 1) ? g_t1 : g_t2);
    float2* __restrict__ out =
        (float2*)((S == 0) ? g_t1 : (S == 1) ? g_t2 : g_t3);

    int lane = threadIdx.x & 31;
    int gw = (blockIdx.x * blockDim.x + threadIdx.x) >> 5;
    int nw = (gridDim.x * blockDim.x) >> 5;

    for (int n = gw; n < NN; n += nw) {
        int beg = g_rowptr[n];
        int end = g_rowptr[n + 1];
        float ax = 0.f, ay = 0.f;
        int j = beg;
        for (; j + 3 < end; j += 4) {
            int2 e0 = __ldg(&g_edge[j + 0]);
            int2 e1 = __ldg(&g_edge[j + 1]);
            int2 e2 = __ldg(&g_edge[j + 2]);
            int2 e3 = __ldg(&g_edge[j + 3]);
            float2 u0 = __ldg(&in[(size_t)e0.x * 32 + lane]);
            float2 u1 = __ldg(&in[(size_t)e1.x * 32 + lane]);
            float2 u2 = __ldg(&in[(size_t)e2.x * 32 + lane]);
            float2 u3 = __ldg(&in[(size_t)e3.x * 32 + lane]);
            float v0 = __int_as_float(e0.y);
            float v1 = __int_as_float(e1.y);
            float v2 = __int_as_float(e2.y);
            float v3 = __int_as_float(e3.y);
            ax = fmaf(v0, u0.x, ax); ay = fmaf(v0, u0.y, ay);
            ax = fmaf(v1, u1.x, ax); ay = fmaf(v1, u1.y, ay);
            ax = fmaf(v2, u2.x, ax); ay = fmaf(v2, u2.y, ay);
            ax = fmaf(v3, u3.x, ax); ay = fmaf(v3, u3.y, ay);
        }
        for (; j < end; j++) {
            int2 e0 = __ldg(&g_edge[j]);
            float2 u0 = __ldg(&in[(size_t)e0.x * 32 + lane]);
            float v0 = __int_as_float(e0.y);
            ax = fmaf(v0, u0.x, ax); ay = fmaf(v0, u0.y, ay);
        }
        out[(size_t)n * 32 + lane] = make_float2(ax, ay);
    }
}

// ---------------- fused epilogue (float2 lanes) -----------------------------
__device__ __forceinline__ float tanh_fast(float x) {
    float y;
    asm("tanh.approx.f32 %0, %1;" : "=f"(y) : "f"(x));
    return y;
}

__device__ __forceinline__ float warpsum(float v) {
    v += __shfl_xor_sync(0xffffffffu, v, 16);
    v += __shfl_xor_sync(0xffffffffu, v, 8);
    v += __shfl_xor_sync(0xffffffffu, v, 4);
    v += __shfl_xor_sync(0xffffffffu, v, 2);
    v += __shfl_xor_sync(0xffffffffu, v, 1);
    return v;
}

// single matvec: o[c] = b[c] + sum_k v[k] * W[k][c], lane owns c=2l,2l+1
__device__ __forceinline__ float2 matvec64v(float2 v,
                                            const float2* __restrict__ W2v,
                                            const float2* __restrict__ b2v,
                                            int lane) {
    float2 o = b2v[lane];
#pragma unroll
    for (int kk = 0; kk < 32; kk++) {
        float vx = __shfl_sync(0xffffffffu, v.x, kk);
        float vy = __shfl_sync(0xffffffffu, v.y, kk);
        float2 wa = W2v[(2 * kk) * 32 + lane];
        float2 wb = W2v[(2 * kk + 1) * 32 + lane];
        o.x = fmaf(vx, wa.x, o.x); o.x = fmaf(vy, wb.x, o.x);
        o.y = fmaf(vx, wa.y, o.y); o.y = fmaf(vy, wb.y, o.y);
    }
    return o;
}

// dual matvec sharing weights (for the two filters through Wb)
__device__ __forceinline__ void matvec64v_dual(float2 v0, float2 v1,
                                               const float2* __restrict__ W2v,
                                               const float2* __restrict__ b2v,
                                               int lane, float2& o0, float2& o1) {
    float2 b = b2v[lane];
    o0 = b; o1 = b;
#pragma unroll
    for (int kk = 0; kk < 32; kk++) {
        float v0x = __shfl_sync(0xffffffffu, v0.x, kk);
        float v0y = __shfl_sync(0xffffffffu, v0.y, kk);
        float v1x = __shfl_sync(0xffffffffu, v1.x, kk);
        float v1y = __shfl_sync(0xffffffffu, v1.y, kk);
        float2 wa = W2v[(2 * kk) * 32 + lane];
        float2 wb = W2v[(2 * kk + 1) * 32 + lane];
        o0.x = fmaf(v0x, wa.x, o0.x); o0.x = fmaf(v0y, wb.x, o0.x);
        o0.y = fmaf(v0x, wa.y, o0.y); o0.y = fmaf(v0y, wb.y, o0.y);
        o1.x = fmaf(v1x, wa.x, o1.x); o1.x = fmaf(v1y, wb.x, o1.x);
        o1.y = fmaf(v1x, wa.y, o1.y); o1.y = fmaf(v1y, wb.y, o1.y);
    }
}

#define OFF_WB  0
#define OFF_WX  4096
#define OFF_W1  8192
#define OFF_W2  12288
#define OFF_W3  14336
#define OFF_VC  14400
#define OFF_BWB 14464
#define OFF_BWX 14528
#define OFF_B1  14592
#define OFF_B2  14656
#define OFF_B3  14688
#define EPI_SMEM_FLOATS 14720
#define EPI_SMEM_BYTES (EPI_SMEM_FLOATS * 4)

__global__ void epilogue_kernel(const float* __restrict__ thetas,
                                const float* __restrict__ Wb, const float* __restrict__ bWb,
                                const float* __restrict__ Wx, const float* __restrict__ bWx,
                                const float* __restrict__ vc,
                                const float* __restrict__ W1, const float* __restrict__ b1,
                                const float* __restrict__ W2, const float* __restrict__ b2,
                                const float* __restrict__ W3, const float* __restrict__ b3,
                                float* __restrict__ out) {
    extern __shared__ float sm[];
    int t = threadIdx.x;
    for (int i = t; i < 4096; i += blockDim.x) {
        sm[OFF_WB + i] = Wb[i];
        sm[OFF_WX + i] = Wx[i];
        sm[OFF_W1 + i] = W1[i];
    }
    for (int i = t; i < 2048; i += blockDim.x) sm[OFF_W2 + i] = W2[i];
    if (t < 64) {
        sm[OFF_W3 + t]  = W3[t];
        sm[OFF_VC + t]  = vc[t];
        sm[OFF_BWB + t] = bWb[t];
        sm[OFF_BWX + t] = bWx[t];
        sm[OFF_B1 + t]  = b1[t];
    }
    if (t < 32) sm[OFF_B2 + t] = b2[t];
    if (t < 2)  sm[OFF_B3 + t] = b3[t];
    __syncthreads();

    float t00 = thetas[0], t01 = thetas[1], t02 = thetas[2], t03 = thetas[3];
    float t10 = thetas[4], t11 = thetas[5], t12 = thetas[6], t13 = thetas[7];
    float c00 = t00;
    float c01 = -3.f * t00 + 3.f * t01;
    float c02 =  3.f * t00 - 6.f * t01 + 3.f * t02;
    float c03 = -1.f * t00 + 3.f * t01 - 3.f * t02 + t03;
    float c10 = t10;
    float c11 = -3.f * t10 + 3.f * t11;
    float c12 =  3.f * t10 - 6.f * t11 + 3.f * t12;
    float c13 = -1.f * t10 + 3.f * t11 - 3.f * t12 + t13;

    const float2* sWb = (const float2*)(sm + OFF_WB);
    const float2* sWx = (const float2*)(sm + OFF_WX);
    const float2* sW1 = (const float2*)(sm + OFF_W1);
    const float*  sW2 = sm + OFF_W2;
    const float*  sW3 = sm + OFF_W3;
    const float2* svc = (const float2*)(sm + OFF_VC);
    const float2* sbWb = (const float2*)(sm + OFF_BWB);
    const float2* sbWx = (const float2*)(sm + OFF_BWX);
    const float2* sb1  = (const float2*)(sm + OFF_B1);

    const float2* h2v  = (const float2*)g_h;
    const float2* t1v  = (const float2*)g_t1;
    const float2* t2v  = (const float2*)g_t2;
    const float2* t3v  = (const float2*)g_t3;

    int lane = threadIdx.x & 31;
    int gw = (blockIdx.x * blockDim.x + threadIdx.x) >> 5;
    int nw = (gridDim.x * blockDim.x) >> 5;

    for (int n = gw; n < NN; n += nw) {
        size_t base = (size_t)n * 32 + lane;
        float2 h  = __ldg(&h2v[base]);
        float2 x1 = __ldg(&t1v[base]);
        float2 x2 = __ldg(&t2v[base]);
        float2 x3 = __ldg(&t3v[base]);

        float2 p0, p1;
        p0.x = fmaf(c00, h.x, fmaf(c01, x1.x, fmaf(c02, x2.x, c03 * x3.x)));
        p0.y = fmaf(c00, h.y, fmaf(c01, x1.y, fmaf(c02, x2.y, c03 * x3.y)));
        p1.x = fmaf(c10, h.x, fmaf(c11, x1.x, fmaf(c12, x2.x, c13 * x3.x)));
        p1.y = fmaf(c10, h.y, fmaf(c11, x1.y, fmaf(c12, x2.y, c13 * x3.y)));

        float2 pp0, pp1;
        matvec64v_dual(p0, p1, sWb, sbWb, lane, pp0, pp1);
        float2 xp = matvec64v(h, sWx, sbWx, lane);

        float2 vcl = svc[lane];
        float s0 = warpsum(tanh_fast(pp0.x + xp.x) * vcl.x +
                           tanh_fast(pp0.y + xp.y) * vcl.y);
        float s1 = warpsum(tanh_fast(pp1.x + xp.x) * vcl.x +
                           tanh_fast(pp1.y + xp.y) * vcl.y);
        float m = fmaxf(s0, s1);
        float e0 = __expf(s0 - m), e1 = __expf(s1 - m);
        float inv = 1.f / (e0 + e1);
        float a0 = e0 * inv, a1 = e1 * inv;

        float2 r;
        r.x = a0 * p0.x + a1 * p1.x;
        r.y = a0 * p0.y + a1 * p1.y;

        float2 y1 = matvec64v(r, sW1, sb1, lane);
        y1.x = fmaxf(y1.x, 0.f);
        y1.y = fmaxf(y1.y, 0.f);

        // y2[c] for c = lane (32 outputs)
        float acc = sm[OFF_B2 + lane];
#pragma unroll
        for (int kk = 0; kk < 32; kk++) {
            float axv = __shfl_sync(0xffffffffu, y1.x, kk);
            float ayv = __shfl_sync(0xffffffffu, y1.y, kk);
            acc = fmaf(axv, sW2[(2 * kk) * 32 + lane], acc);
            acc = fmaf(ayv, sW2[(2 * kk + 1) * 32 + lane], acc);
        }
        float y2 = fmaxf(acc, 0.f);

        float q0 = warpsum(y2 * sW3[lane * 2 + 0]);
        float q1 = warpsum(y2 * sW3[lane * 2 + 1]);
        if (lane == 0) {
            out[(size_t)n * 2 + 0] = sm[OFF_B3 + 0] + q0;
            out[(size_t)n * 2 + 1] = sm[OFF_B3 + 1] + q1;
        }
    }
}

// ---------------- launch ----------------------------------------------------
extern "C" void kernel_launch(void* const* d_in, const int* in_sizes, int n_in,
                              void* d_out, int out_size) {
    const float* x      = (const float*)d_in[0];
    const void*  esrc   = d_in[1];
    const void*  edst   = d_in[2];
    const float* evals  = (const float*)d_in[3];
    const float* Win    = (const float*)d_in[4];
    const float* bin    = (const float*)d_in[5];
    const float* thetas = (const float*)d_in[6];
    const float* Wb     = (const float*)d_in[7];
    const float* bWb    = (const float*)d_in[8];
    const float* Wx     = (const float*)d_in[9];
    const float* bWx    = (const float*)d_in[10];
    const float* vc     = (const float*)d_in[11];
    const float* W1     = (const float*)d_in[12];
    const float* b1     = (const float*)d_in[13];
    const float* W2     = (const float*)d_in[14];
    const float* b2     = (const float*)d_in[15];
    const float* W3     = (const float*)d_in[16];
    const float* b3     = (const float*)d_in[17];
    float* out = (float*)d_out;

    cudaFuncSetAttribute(epilogue_kernel,
                         cudaFuncAttributeMaxDynamicSharedMemorySize,
                         EPI_SMEM_BYTES);

    detect_kernel<<<1, 32>>>((const unsigned int*)esrc);
    zero_cnt_kernel<<<(NN + 255) / 256, 256>>>();
    convert_hist_kernel<<<(EE + 255) / 256, 256>>>(esrc, edst);
    scan_block_kernel<<<NB_SCAN, 512>>>();
    scan_bsum_kernel<<<1, 256>>>();
    add_offsets_kernel<<<(NN + 255) / 256, 256>>>();
    scatter_kernel<<<(EE + 255) / 256, 256>>>(evals);

    gemm_in_kernel<<<1184, 256>>>(x, Win, bin);

    spmm_csr_kernel<0><<<1184, 256>>>();
    spmm_csr_kernel<1><<<1184, 256>>>();
    spmm_csr_kernel<2><<<1184, 256>>>();

    epilogue_kernel<<<592, 256, EPI_SMEM_BYTES>>>(
        thetas, Wb, bWb, Wx, bWx, vc, W1, b1, W2, b2, W3, b3, out);
}

// round 6
// speedup vs baseline: 1.0070x; 1.0070x over previous
#include <cuda_runtime.h>
#include <cuda_bf16.h>
#include <cstdint>

#define NN 100000
#define EE 1600000
#define CIN 128
#define CC 64
#define NB_SCAN 196   // ceil(NN/512)

// ---------------- scratch (device globals; no allocation allowed) ----------
__device__ float g_h [NN * CC];
__device__ float g_t1[NN * CC];
__device__ float g_t2[NN * CC];
__device__ float g_t3[NN * CC];
__device__ int   g_src[EE];
__device__ int   g_dst[EE];
__device__ int2  g_edge[EE];      // sorted-by-dst: {src, __float_as_int(val)}
__device__ int   g_rowptr[NN + 1];
__device__ int   g_cnt[NN];       // histogram, then running scatter offsets
__device__ int   g_bsum[NB_SCAN];
__device__ int   g_bsumex[NB_SCAN];
__device__ int   g_flag[1];

// ---------------- index width detection ------------------------------------
// int64 indices with values < 2^31: every odd 32-bit word is 0. 64 random
// int32 indices in [0,1e5) being all zero is impossible.
__global__ void detect_kernel(const unsigned int* p) {
    if (threadIdx.x == 0 && blockIdx.x == 0) {
        int is64 = 1;
        for (int i = 1; i < 128; i += 2)
            if (p[i] != 0u) { is64 = 0; break; }
        g_flag[0] = is64;
    }
}

__global__ void zero_cnt_kernel() {
    int i = blockIdx.x * blockDim.x + threadIdx.x;
    if (i < NN) g_cnt[i] = 0;
}

__global__ void convert_hist_kernel(const void* srcp, const void* dstp) {
    int e = blockIdx.x * blockDim.x + threadIdx.x;
    if (e >= EE) return;
    int s, d;
    if (g_flag[0]) {
        s = (int)((const long long*)srcp)[e];
        d = (int)((const long long*)dstp)[e];
    } else {
        s = ((const int*)srcp)[e];
        d = ((const int*)dstp)[e];
    }
    g_src[e] = s;
    g_dst[e] = d;
    atomicAdd(&g_cnt[d], 1);
}

// ---------------- 2-level exclusive scan over g_cnt ------------------------
__global__ void scan_block_kernel() {   // 512 threads per block
    __shared__ int s[512];
    int tid = threadIdx.x;
    int i = blockIdx.x * 512 + tid;
    int v = (i < NN) ? g_cnt[i] : 0;
    s[tid] = v;
    __syncthreads();
#pragma unroll
    for (int off = 1; off < 512; off <<= 1) {
        int t = (tid >= off) ? s[tid - off] : 0;
        __syncthreads();
        s[tid] += t;
        __syncthreads();
    }
    if (i < NN) g_rowptr[i] = s[tid] - v;
    if (tid == 511) g_bsum[blockIdx.x] = s[511];
}

__global__ void scan_bsum_kernel() {    // single block, 256 threads
    __shared__ int s[256];
    int tid = threadIdx.x;
    int v = (tid < NB_SCAN) ? g_bsum[tid] : 0;
    s[tid] = v;
    __syncthreads();
#pragma unroll
    for (int off = 1; off < 256; off <<= 1) {
        int t = (tid >= off) ? s[tid - off] : 0;
        __syncthreads();
        s[tid] += t;
        __syncthreads();
    }
    if (tid < NB_SCAN) g_bsumex[tid] = s[tid] - v;
}

__global__ void add_offsets_kernel() {
    int i = blockIdx.x * blockDim.x + threadIdx.x;
    if (i < NN) {
        int r = g_rowptr[i] + g_bsumex[i >> 9];
        g_rowptr[i] = r;
        g_cnt[i] = r;
    }
    if (i == 0) g_rowptr[NN] = EE;
}

__global__ void scatter_kernel(const float* __restrict__ vals) {
    int e = blockIdx.x * blockDim.x + threadIdx.x;
    if (e >= EE) return;
    int d = g_dst[e];
    int pos = atomicAdd(&g_cnt[d], 1);
    g_edge[pos] = make_int2(g_src[e], __float_as_int(vals[e]));
}

// ---------------- input GEMM: h = relu(x @ W_in + b_in) ---------------------
__global__ void gemm_in_kernel(const float* __restrict__ x,
                               const float* __restrict__ Win,
                               const float* __restrict__ bin) {
    __shared__ float2 Ws[CIN * 32];
    __shared__ float bs[CC];
    for (int i = threadIdx.x; i < CIN * 32; i += blockDim.x) {
        int k = i >> 5, l = i & 31;
        Ws[i] = make_float2(Win[k * CC + l], Win[k * CC + l + 32]);
    }
    if (threadIdx.x < CC) bs[threadIdx.x] = bin[threadIdx.x];
    __syncthreads();

    int lane = threadIdx.x & 31;
    int gw = (blockIdx.x * blockDim.x + threadIdx.x) >> 5;
    int nw = (gridDim.x * blockDim.x) >> 5;
    const int NG = NN / 4;   // 25000, exact

    for (int g = gw; g < NG; g += nw) {
        int n0 = g * 4;
        const float4* xr0 = (const float4*)(x + (size_t)(n0 + 0) * CIN);
        const float4* xr1 = (const float4*)(x + (size_t)(n0 + 1) * CIN);
        const float4* xr2 = (const float4*)(x + (size_t)(n0 + 2) * CIN);
        const float4* xr3 = (const float4*)(x + (size_t)(n0 + 3) * CIN);
        float b0 = bs[lane], b1 = bs[lane + 32];
        float a00 = b0, a01 = b1, a10 = b0, a11 = b1;
        float a20 = b0, a21 = b1, a30 = b0, a31 = b1;
#pragma unroll 4
        for (int k4 = 0; k4 < CIN / 4; k4++) {
            float xa[4], xb[4], xc[4], xd[4];
            *(float4*)xa = __ldg(&xr0[k4]);
            *(float4*)xb = __ldg(&xr1[k4]);
            *(float4*)xc = __ldg(&xr2[k4]);
            *(float4*)xd = __ldg(&xr3[k4]);
#pragma unroll
            for (int kk = 0; kk < 4; kk++) {
                float2 w = Ws[(k4 * 4 + kk) * 32 + lane];
                a00 = fmaf(xa[kk], w.x, a00); a01 = fmaf(xa[kk], w.y, a01);
                a10 = fmaf(xb[kk], w.x, a10); a11 = fmaf(xb[kk], w.y, a11);
                a20 = fmaf(xc[kk], w.x, a20); a21 = fmaf(xc[kk], w.y, a21);
                a30 = fmaf(xd[kk], w.x, a30); a31 = fmaf(xd[kk], w.y, a31);
            }
        }
        g_h[(size_t)(n0 + 0) * CC + lane]      = fmaxf(a00, 0.f);
        g_h[(size_t)(n0 + 0) * CC + lane + 32] = fmaxf(a01, 0.f);
        g_h[(size_t)(n0 + 1) * CC + lane]      = fmaxf(a10, 0.f);
        g_h[(size_t)(n0 + 1) * CC + lane + 32] = fmaxf(a11, 0.f);
        g_h[(size_t)(n0 + 2) * CC + lane]      = fmaxf(a20, 0.f);
        g_h[(size_t)(n0 + 2) * CC + lane + 32] = fmaxf(a21, 0.f);
        g_h[(size_t)(n0 + 3) * CC + lane]      = fmaxf(a30, 0.f);
        g_h[(size_t)(n0 + 3) * CC + lane + 32] = fmaxf(a31, 0.f);
    }
}

// ---------------- CSR SpMM (no atomics, float2 lanes) -----------------------
// One warp per dst row; lane owns channels (2*lane, 2*lane+1).
template <int S>
__global__ void spmm_csr_kernel() {
    const float2* __restrict__ in =
        (const float2*)((S == 0) ? g_h : (S == 1) ? g_t1 : g_t2);
    float2* __restrict__ out =
        (float2*)((S == 0) ? g_t1 : (S == 1) ? g_t2 : g_t3);

    int lane = threadIdx.x & 31;
    int gw = (blockIdx.x * blockDim.x + threadIdx.x) >> 5;
    int nw = (gridDim.x * blockDim.x) >> 5;

    for (int n = gw; n < NN; n += nw) {
        int beg = g_rowptr[n];
        int end = g_rowptr[n + 1];
        float ax = 0.f, ay = 0.f;
        int j = beg;
        for (; j + 3 < end; j += 4) {
            int2 e0 = __ldg(&g_edge[j + 0]);
            int2 e1 = __ldg(&g_edge[j + 1]);
            int2 e2 = __ldg(&g_edge[j + 2]);
            int2 e3 = __ldg(&g_edge[j + 3]);
            float2 u0 = __ldg(&in[(size_t)e0.x * 32 + lane]);
            float2 u1 = __ldg(&in[(size_t)e1.x * 32 + lane]);
            float2 u2 = __ldg(&in[(size_t)e2.x * 32 + lane]);
            float2 u3 = __ldg(&in[(size_t)e3.x * 32 + lane]);
            float v0 = __int_as_float(e0.y);
            float v1 = __int_as_float(e1.y);
            float v2 = __int_as_float(e2.y);
            float v3 = __int_as_float(e3.y);
            ax = fmaf(v0, u0.x, ax); ay = fmaf(v0, u0.y, ay);
            ax = fmaf(v1, u1.x, ax); ay = fmaf(v1, u1.y, ay);
            ax = fmaf(v2, u2.x, ax); ay = fmaf(v2, u2.y, ay);
            ax = fmaf(v3, u3.x, ax); ay = fmaf(v3, u3.y, ay);
        }
        for (; j < end; j++) {
            int2 e0 = __ldg(&g_edge[j]);
            float2 u0 = __ldg(&in[(size_t)e0.x * 32 + lane]);
            float v0 = __int_as_float(e0.y);
            ax = fmaf(v0, u0.x, ax); ay = fmaf(v0, u0.y, ay);
        }
        out[(size_t)n * 32 + lane] = make_float2(ax, ay);
    }
}

// ---------------- fused epilogue (float2 lanes) -----------------------------
__device__ __forceinline__ float tanh_fast(float x) {
    float y;
    asm("tanh.approx.f32 %0, %1;" : "=f"(y) : "f"(x));
    return y;
}

__device__ __forceinline__ float warpsum(float v) {
    v += __shfl_xor_sync(0xffffffffu, v, 16);
    v += __shfl_xor_sync(0xffffffffu, v, 8);
    v += __shfl_xor_sync(0xffffffffu, v, 4);
    v += __shfl_xor_sync(0xffffffffu, v, 2);
    v += __shfl_xor_sync(0xffffffffu, v, 1);
    return v;
}

// single matvec: o[c] = b[c] + sum_k v[k] * W[k][c], lane owns c=2l,2l+1
__device__ __forceinline__ float2 matvec64v(float2 v,
                                            const float2* __restrict__ W2v,
                                            const float2* __restrict__ b2v,
                                            int lane) {
    float2 o = b2v[lane];
#pragma unroll
    for (int kk = 0; kk < 32; kk++) {
        float vx = __shfl_sync(0xffffffffu, v.x, kk);
        float vy = __shfl_sync(0xffffffffu, v.y, kk);
        float2 wa = W2v[(2 * kk) * 32 + lane];
        float2 wb = W2v[(2 * kk + 1) * 32 + lane];
        o.x = fmaf(vx, wa.x, o.x); o.x = fmaf(vy, wb.x, o.x);
        o.y = fmaf(vx, wa.y, o.y); o.y = fmaf(vy, wb.y, o.y);
    }
    return o;
}

// dual matvec sharing weights (for the two filters through Wb)
__device__ __forceinline__ void matvec64v_dual(float2 v0, float2 v1,
                                               const float2* __restrict__ W2v,
                                               const float2* __restrict__ b2v,
                                               int lane, float2& o0, float2& o1) {
    float2 b = b2v[lane];
    o0 = b; o1 = b;
#pragma unroll
    for (int kk = 0; kk < 32; kk++) {
        float v0x = __shfl_sync(0xffffffffu, v0.x, kk);
        float v0y = __shfl_sync(0xffffffffu, v0.y, kk);
        float v1x = __shfl_sync(0xffffffffu, v1.x, kk);
        float v1y = __shfl_sync(0xffffffffu, v1.y, kk);
        float2 wa = W2v[(2 * kk) * 32 + lane];
        float2 wb = W2v[(2 * kk + 1) * 32 + lane];
        o0.x = fmaf(v0x, wa.x, o0.x); o0.x = fmaf(v0y, wb.x, o0.x);
        o0.y = fmaf(v0x, wa.y, o0.y); o0.y = fmaf(v0y, wb.y, o0.y);
        o1.x = fmaf(v1x, wa.x, o1.x); o1.x = fmaf(v1y, wb.x, o1.x);
        o1.y = fmaf(v1x, wa.y, o1.y); o1.y = fmaf(v1y, wb.y, o1.y);
    }
}

#define OFF_WB  0
#define OFF_WX  4096
#define OFF_W1  8192
#define OFF_W2  12288
#define OFF_W3  14336
#define OFF_VC  14400
#define OFF_BWB 14464
#define OFF_BWX 14528
#define OFF_B1  14592
#define OFF_B2  14656
#define OFF_B3  14688
#define EPI_SMEM_FLOATS 14720
#define EPI_SMEM_BYTES (EPI_SMEM_FLOATS * 4)

__global__ void epilogue_kernel(const float* __restrict__ thetas,
                                const float* __restrict__ Wb, const float* __restrict__ bWb,
                                const float* __restrict__ Wx, const float* __restrict__ bWx,
                                const float* __restrict__ vc,
                                const float* __restrict__ W1, const float* __restrict__ b1,
                                const float* __restrict__ W2, const float* __restrict__ b2,
                                const float* __restrict__ W3, const float* __restrict__ b3,
                                float* __restrict__ out) {
    extern __shared__ float sm[];
    int t = threadIdx.x;
    for (int i = t; i < 4096; i += blockDim.x) {
        sm[OFF_WB + i] = Wb[i];
        sm[OFF_WX + i] = Wx[i];
        sm[OFF_W1 + i] = W1[i];
    }
    for (int i = t; i < 2048; i += blockDim.x) sm[OFF_W2 + i] = W2[i];
    if (t < 64) {
        sm[OFF_W3 + t]  = W3[t];
        sm[OFF_VC + t]  = vc[t];
        sm[OFF_BWB + t] = bWb[t];
        sm[OFF_BWX + t] = bWx[t];
        sm[OFF_B1 + t]  = b1[t];
    }
    if (t < 32) sm[OFF_B2 + t] = b2[t];
    if (t < 2)  sm[OFF_B3 + t] = b3[t];
    __syncthreads();

    float t00 = thetas[0], t01 = thetas[1], t02 = thetas[2], t03 = thetas[3];
    float t10 = thetas[4], t11 = thetas[5], t12 = thetas[6], t13 = thetas[7];
    float c00 = t00;
    float c01 = -3.f * t00 + 3.f * t01;
    float c02 =  3.f * t00 - 6.f * t01 + 3.f * t02;
    float c03 = -1.f * t00 + 3.f * t01 - 3.f * t02 + t03;
    float c10 = t10;
    float c11 = -3.f * t10 + 3.f * t11;
    float c12 =  3.f * t10 - 6.f * t11 + 3.f * t12;
    float c13 = -1.f * t10 + 3.f * t11 - 3.f * t12 + t13;

    const float2* sWb = (const float2*)(sm + OFF_WB);
    const float2* sWx = (const float2*)(sm + OFF_WX);
    const float2* sW1 = (const float2*)(sm + OFF_W1);
    const float*  sW2 = sm + OFF_W2;
    const float*  sW3 = sm + OFF_W3;
    const float2* svc = (const float2*)(sm + OFF_VC);
    const float2* sbWb = (const float2*)(sm + OFF_BWB);
    const float2* sbWx = (const float2*)(sm + OFF_BWX);
    const float2* sb1  = (const float2*)(sm + OFF_B1);

    const float2* h2v  = (const float2*)g_h;
    const float2* t1v  = (const float2*)g_t1;
    const float2* t2v  = (const float2*)g_t2;
    const float2* t3v  = (const float2*)g_t3;

    int lane = threadIdx.x & 31;
    int gw = (blockIdx.x * blockDim.x + threadIdx.x) >> 5;
    int nw = (gridDim.x * blockDim.x) >> 5;

    for (int n = gw; n < NN; n += nw) {
        size_t base = (size_t)n * 32 + lane;
        float2 h  = __ldg(&h2v[base]);
        float2 x1 = __ldg(&t1v[base]);
        float2 x2 = __ldg(&t2v[base]);
        float2 x3 = __ldg(&t3v[base]);

        float2 p0, p1;
        p0.x = fmaf(c00, h.x, fmaf(c01, x1.x, fmaf(c02, x2.x, c03 * x3.x)));
        p0.y = fmaf(c00, h.y, fmaf(c01, x1.y, fmaf(c02, x2.y, c03 * x3.y)));
        p1.x = fmaf(c10, h.x, fmaf(c11, x1.x, fmaf(c12, x2.x, c13 * x3.x)));
        p1.y = fmaf(c10, h.y, fmaf(c11, x1.y, fmaf(c12, x2.y, c13 * x3.y)));

        float2 pp0, pp1;
        matvec64v_dual(p0, p1, sWb, sbWb, lane, pp0, pp1);
        float2 xp = matvec64v(h, sWx, sbWx, lane);

        float2 vcl = svc[lane];
        float s0 = warpsum(tanh_fast(pp0.x + xp.x) * vcl.x +
                           tanh_fast(pp0.y + xp.y) * vcl.y);
        float s1 = warpsum(tanh_fast(pp1.x + xp.x) * vcl.x +
                           tanh_fast(pp1.y + xp.y) * vcl.y);
        float m = fmaxf(s0, s1);
        float e0 = __expf(s0 - m), e1 = __expf(s1 - m);
        float inv = 1.f / (e0 + e1);
        float a0 = e0 * inv, a1 = e1 * inv;

        float2 r;
        r.x = a0 * p0.x + a1 * p1.x;
        r.y = a0 * p0.y + a1 * p1.y;

        float2 y1 = matvec64v(r, sW1, sb1, lane);
        y1.x = fmaxf(y1.x, 0.f);
        y1.y = fmaxf(y1.y, 0.f);

        // y2[c] for c = lane (32 outputs)
        float acc = sm[OFF_B2 + lane];
#pragma unroll
        for (int kk = 0; kk < 32; kk++) {
            float axv = __shfl_sync(0xffffffffu, y1.x, kk);
            float ayv = __shfl_sync(0xffffffffu, y1.y, kk);
            acc = fmaf(axv, sW2[(2 * kk) * 32 + lane], acc);
            acc = fmaf(ayv, sW2[(2 * kk + 1) * 32 + lane], acc);
        }
        float y2 = fmaxf(acc, 0.f);

        float q0 = warpsum(y2 * sW3[lane * 2 + 0]);
        float q1 = warpsum(y2 * sW3[lane * 2 + 1]);
        if (lane == 0) {
            out[(size_t)n * 2 + 0] = sm[OFF_B3 + 0] + q0;
            out[(size_t)n * 2 + 1] = sm[OFF_B3 + 1] + q1;
        }
    }
}

// ---------------- launch ----------------------------------------------------
extern "C" void kernel_launch(void* const* d_in, const int* in_sizes, int n_in,
                              void* d_out, int out_size) {
    const float* x      = (const float*)d_in[0];
    const void*  esrc   = d_in[1];
    const void*  edst   = d_in[2];
    const float* evals  = (const float*)d_in[3];
    const float* Win    = (const float*)d_in[4];
    const float* bin    = (const float*)d_in[5];
    const float* thetas = (const float*)d_in[6];
    const float* Wb     = (const float*)d_in[7];
    const float* bWb    = (const float*)d_in[8];
    const float* Wx     = (const float*)d_in[9];
    const float* bWx    = (const float*)d_in[10];
    const float* vc     = (const float*)d_in[11];
    const float* W1     = (const float*)d_in[12];
    const float* b1     = (const float*)d_in[13];
    const float* W2     = (const float*)d_in[14];
    const float* b2     = (const float*)d_in[15];
    const float* W3     = (const float*)d_in[16];
    const float* b3     = (const float*)d_in[17];
    float* out = (float*)d_out;

    cudaFuncSetAttribute(epilogue_kernel,
                         cudaFuncAttributeMaxDynamicSharedMemorySize,
                         EPI_SMEM_BYTES);

    detect_kernel<<<1, 32>>>((const unsigned int*)esrc);
    zero_cnt_kernel<<<(NN + 255) / 256, 256>>>();
    convert_hist_kernel<<<(EE + 255) / 256, 256>>>(esrc, edst);
    scan_block_kernel<<<NB_SCAN, 512>>>();
    scan_bsum_kernel<<<1, 256>>>();
    add_offsets_kernel<<<(NN + 255) / 256, 256>>>();
    scatter_kernel<<<(EE + 255) / 256, 256>>>(evals);

    gemm_in_kernel<<<1184, 256>>>(x, Win, bin);

    spmm_csr_kernel<0><<<1184, 256>>>();
    spmm_csr_kernel<1><<<1184, 256>>>();
    spmm_csr_kernel<2><<<1184, 256>>>();

    epilogue_kernel<<<592, 256, EPI_SMEM_BYTES>>>(
        thetas, Wb, bWb, Wx, bWx, vc, W1, b1, W2, b2, W3, b3, out);
}

// round 7
// speedup vs baseline: 1.3696x; 1.3601x over previous
#include <cuda_runtime.h>
#include <cuda_bf16.h>
#include <cstdint>

#define NN 100000
#define EE 1600000
#define CIN 128
#define CC 64
#define NB_SCAN 196   // ceil(NN/512)

// ---------------- scratch (device globals; no allocation allowed) ----------
__device__ float g_h [NN * CC];
__device__ float g_t1[NN * CC];
__device__ float g_t2[NN * CC];
__device__ float g_t3[NN * CC];
__device__ int   g_src[EE];
__device__ int   g_dst[EE];
__device__ int2  g_edge[EE];      // sorted-by-dst: {src, __float_as_int(val)}
__device__ int   g_rowptr[NN + 1];
__device__ int   g_cnt[NN];       // histogram, then running scatter offsets
__device__ int   g_bsum[NB_SCAN];
__device__ int   g_bsumex[NB_SCAN];
__device__ int   g_flag[1];

// ---------------- index width detection ------------------------------------
// int64 indices with values < 2^31: every odd 32-bit word is 0. 64 random
// int32 indices in [0,1e5) being all zero is impossible.
__global__ void detect_kernel(const unsigned int* p) {
    if (threadIdx.x == 0 && blockIdx.x == 0) {
        int is64 = 1;
        for (int i = 1; i < 128; i += 2)
            if (p[i] != 0u) { is64 = 0; break; }
        g_flag[0] = is64;
    }
}

__global__ void zero_cnt_kernel() {
    int i = blockIdx.x * blockDim.x + threadIdx.x;
    if (i < NN) g_cnt[i] = 0;
}

__global__ void convert_hist_kernel(const void* srcp, const void* dstp) {
    int e = blockIdx.x * blockDim.x + threadIdx.x;
    if (e >= EE) return;
    int s, d;
    if (g_flag[0]) {
        s = (int)((const long long*)srcp)[e];
        d = (int)((const long long*)dstp)[e];
    } else {
        s = ((const int*)srcp)[e];
        d = ((const int*)dstp)[e];
    }
    g_src[e] = s;
    g_dst[e] = d;
    atomicAdd(&g_cnt[d], 1);
}

// ---------------- 2-level exclusive scan over g_cnt ------------------------
__global__ void scan_block_kernel() {   // 512 threads per block
    __shared__ int s[512];
    int tid = threadIdx.x;
    int i = blockIdx.x * 512 + tid;
    int v = (i < NN) ? g_cnt[i] : 0;
    s[tid] = v;
    __syncthreads();
#pragma unroll
    for (int off = 1; off < 512; off <<= 1) {
        int t = (tid >= off) ? s[tid - off] : 0;
        __syncthreads();
        s[tid] += t;
        __syncthreads();
    }
    if (i < NN) g_rowptr[i] = s[tid] - v;
    if (tid == 511) g_bsum[blockIdx.x] = s[511];
}

__global__ void scan_bsum_kernel() {    // single block, 256 threads
    __shared__ int s[256];
    int tid = threadIdx.x;
    int v = (tid < NB_SCAN) ? g_bsum[tid] : 0;
    s[tid] = v;
    __syncthreads();
#pragma unroll
    for (int off = 1; off < 256; off <<= 1) {
        int t = (tid >= off) ? s[tid - off] : 0;
        __syncthreads();
        s[tid] += t;
        __syncthreads();
    }
    if (tid < NB_SCAN) g_bsumex[tid] = s[tid] - v;
}

__global__ void add_offsets_kernel() {
    int i = blockIdx.x * blockDim.x + threadIdx.x;
    if (i < NN) {
        int r = g_rowptr[i] + g_bsumex[i >> 9];
        g_rowptr[i] = r;
        g_cnt[i] = r;
    }
    if (i == 0) g_rowptr[NN] = EE;
}

__global__ void scatter_kernel(const float* __restrict__ vals) {
    int e = blockIdx.x * blockDim.x + threadIdx.x;
    if (e >= EE) return;
    int d = g_dst[e];
    int pos = atomicAdd(&g_cnt[d], 1);
    g_edge[pos] = make_int2(g_src[e], __float_as_int(vals[e]));
}

// ---------------- input GEMM: h = relu(x @ W_in + b_in) ---------------------
__global__ void gemm_in_kernel(const float* __restrict__ x,
                               const float* __restrict__ Win,
                               const float* __restrict__ bin) {
    __shared__ float2 Ws[CIN * 32];
    __shared__ float bs[CC];
    for (int i = threadIdx.x; i < CIN * 32; i += blockDim.x) {
        int k = i >> 5, l = i & 31;
        Ws[i] = make_float2(Win[k * CC + l], Win[k * CC + l + 32]);
    }
    if (threadIdx.x < CC) bs[threadIdx.x] = bin[threadIdx.x];
    __syncthreads();

    int lane = threadIdx.x & 31;
    int gw = (blockIdx.x * blockDim.x + threadIdx.x) >> 5;
    int nw = (gridDim.x * blockDim.x) >> 5;
    const int NG = NN / 4;   // 25000, exact

    for (int g = gw; g < NG; g += nw) {
        int n0 = g * 4;
        const float4* xr0 = (const float4*)(x + (size_t)(n0 + 0) * CIN);
        const float4* xr1 = (const float4*)(x + (size_t)(n0 + 1) * CIN);
        const float4* xr2 = (const float4*)(x + (size_t)(n0 + 2) * CIN);
        const float4* xr3 = (const float4*)(x + (size_t)(n0 + 3) * CIN);
        float b0 = bs[lane], b1 = bs[lane + 32];
        float a00 = b0, a01 = b1, a10 = b0, a11 = b1;
        float a20 = b0, a21 = b1, a30 = b0, a31 = b1;
#pragma unroll 4
        for (int k4 = 0; k4 < CIN / 4; k4++) {
            float xa[4], xb[4], xc[4], xd[4];
            *(float4*)xa = __ldg(&xr0[k4]);
            *(float4*)xb = __ldg(&xr1[k4]);
            *(float4*)xc = __ldg(&xr2[k4]);
            *(float4*)xd = __ldg(&xr3[k4]);
#pragma unroll
            for (int kk = 0; kk < 4; kk++) {
                float2 w = Ws[(k4 * 4 + kk) * 32 + lane];
                a00 = fmaf(xa[kk], w.x, a00); a01 = fmaf(xa[kk], w.y, a01);
                a10 = fmaf(xb[kk], w.x, a10); a11 = fmaf(xb[kk], w.y, a11);
                a20 = fmaf(xc[kk], w.x, a20); a21 = fmaf(xc[kk], w.y, a21);
                a30 = fmaf(xd[kk], w.x, a30); a31 = fmaf(xd[kk], w.y, a31);
            }
        }
        g_h[(size_t)(n0 + 0) * CC + lane]      = fmaxf(a00, 0.f);
        g_h[(size_t)(n0 + 0) * CC + lane + 32] = fmaxf(a01, 0.f);
        g_h[(size_t)(n0 + 1) * CC + lane]      = fmaxf(a10, 0.f);
        g_h[(size_t)(n0 + 1) * CC + lane + 32] = fmaxf(a11, 0.f);
        g_h[(size_t)(n0 + 2) * CC + lane]      = fmaxf(a20, 0.f);
        g_h[(size_t)(n0 + 2) * CC + lane + 32] = fmaxf(a21, 0.f);
        g_h[(size_t)(n0 + 3) * CC + lane]      = fmaxf(a30, 0.f);
        g_h[(size_t)(n0 + 3) * CC + lane + 32] = fmaxf(a31, 0.f);
    }
}

// ---------------- CSR SpMM (no atomics, float2 lanes) -----------------------
template <int S>
__global__ void spmm_csr_kernel() {
    const float2* __restrict__ in =
        (const float2*)((S == 0) ? g_h : (S == 1) ? g_t1 : g_t2);
    float2* __restrict__ out =
        (float2*)((S == 0) ? g_t1 : (S == 1) ? g_t2 : g_t3);

    int lane = threadIdx.x & 31;
    int gw = (blockIdx.x * blockDim.x + threadIdx.x) >> 5;
    int nw = (gridDim.x * blockDim.x) >> 5;

    for (int n = gw; n < NN; n += nw) {
        int beg = g_rowptr[n];
        int end = g_rowptr[n + 1];
        float ax = 0.f, ay = 0.f;
        int j = beg;
        for (; j + 3 < end; j += 4) {
            int2 e0 = __ldg(&g_edge[j + 0]);
            int2 e1 = __ldg(&g_edge[j + 1]);
            int2 e2 = __ldg(&g_edge[j + 2]);
            int2 e3 = __ldg(&g_edge[j + 3]);
            float2 u0 = __ldg(&in[(size_t)e0.x * 32 + lane]);
            float2 u1 = __ldg(&in[(size_t)e1.x * 32 + lane]);
            float2 u2 = __ldg(&in[(size_t)e2.x * 32 + lane]);
            float2 u3 = __ldg(&in[(size_t)e3.x * 32 + lane]);
            float v0 = __int_as_float(e0.y);
            float v1 = __int_as_float(e1.y);
            float v2 = __int_as_float(e2.y);
            float v3 = __int_as_float(e3.y);
            ax = fmaf(v0, u0.x, ax); ay = fmaf(v0, u0.y, ay);
            ax = fmaf(v1, u1.x, ax); ay = fmaf(v1, u1.y, ay);
            ax = fmaf(v2, u2.x, ax); ay = fmaf(v2, u2.y, ay);
            ax = fmaf(v3, u3.x, ax); ay = fmaf(v3, u3.y, ay);
        }
        for (; j < end; j++) {
            int2 e0 = __ldg(&g_edge[j]);
            float2 u0 = __ldg(&in[(size_t)e0.x * 32 + lane]);
            float v0 = __int_as_float(e0.y);
            ax = fmaf(v0, u0.x, ax); ay = fmaf(v0, u0.y, ay);
        }
        out[(size_t)n * 32 + lane] = make_float2(ax, ay);
    }
}

// ---------------- fused epilogue: 4 nodes/warp, smem-staged vectors ---------
__device__ __forceinline__ float tanh_fast(float x) {
    float y;
    asm("tanh.approx.f32 %0, %1;" : "=f"(y) : "f"(x));
    return y;
}

__device__ __forceinline__ float warpsum(float v) {
    v += __shfl_xor_sync(0xffffffffu, v, 16);
    v += __shfl_xor_sync(0xffffffffu, v, 8);
    v += __shfl_xor_sync(0xffffffffu, v, 4);
    v += __shfl_xor_sync(0xffffffffu, v, 2);
    v += __shfl_xor_sync(0xffffffffu, v, 1);
    return v;
}

#define OFF_WB  0
#define OFF_WX  4096
#define OFF_W1  8192
#define OFF_W2  12288
#define OFF_W3  14336
#define OFF_VC  14400
#define OFF_BWB 14464
#define OFF_BWX 14528
#define OFF_B1  14592
#define OFF_B2  14656
#define OFF_B3  14688
#define W_SMEM_FLOATS 14720
#define EPI_WARPS 8
#define STAGE_FLOATS (EPI_WARPS * 768)     // 3 vecs x 4 nodes x 64 per warp
#define EPI_SMEM_BYTES ((W_SMEM_FLOATS + STAGE_FLOATS) * 4)

__global__ __launch_bounds__(256, 2)
void epilogue_kernel(const float* __restrict__ thetas,
                     const float* __restrict__ Wb, const float* __restrict__ bWb,
                     const float* __restrict__ Wx, const float* __restrict__ bWx,
                     const float* __restrict__ vc,
                     const float* __restrict__ W1, const float* __restrict__ b1,
                     const float* __restrict__ W2, const float* __restrict__ b2,
                     const float* __restrict__ W3, const float* __restrict__ b3,
                     float* __restrict__ out) {
    extern __shared__ float sm[];
    int t = threadIdx.x;
    for (int i = t; i < 4096; i += blockDim.x) {
        sm[OFF_WB + i] = Wb[i];
        sm[OFF_WX + i] = Wx[i];
        sm[OFF_W1 + i] = W1[i];
    }
    for (int i = t; i < 2048; i += blockDim.x) sm[OFF_W2 + i] = W2[i];
    if (t < 64) {
        sm[OFF_W3 + t]  = W3[t];
        sm[OFF_VC + t]  = vc[t];
        sm[OFF_BWB + t] = bWb[t];
        sm[OFF_BWX + t] = bWx[t];
        sm[OFF_B1 + t]  = b1[t];
    }
    if (t < 32) sm[OFF_B2 + t] = b2[t];
    if (t < 2)  sm[OFF_B3 + t] = b3[t];
    __syncthreads();

    float t00 = thetas[0], t01 = thetas[1], t02 = thetas[2], t03 = thetas[3];
    float t10 = thetas[4], t11 = thetas[5], t12 = thetas[6], t13 = thetas[7];
    float c00 = t00;
    float c01 = -3.f * t00 + 3.f * t01;
    float c02 =  3.f * t00 - 6.f * t01 + 3.f * t02;
    float c03 = -1.f * t00 + 3.f * t01 - 3.f * t02 + t03;
    float c10 = t10;
    float c11 = -3.f * t10 + 3.f * t11;
    float c12 =  3.f * t10 - 6.f * t11 + 3.f * t12;
    float c13 = -1.f * t10 + 3.f * t11 - 3.f * t12 + t13;

    const float2* sWbv = (const float2*)(sm + OFF_WB);
    const float2* sWxv = (const float2*)(sm + OFF_WX);
    const float2* sW1v = (const float2*)(sm + OFF_W1);
    const float*  sW2  = sm + OFF_W2;
    const float*  sW3  = sm + OFF_W3;
    const float2* svc  = (const float2*)(sm + OFF_VC);
    const float2* sbWb = (const float2*)(sm + OFF_BWB);
    const float2* sbWx = (const float2*)(sm + OFF_BWX);
    const float2* sb1  = (const float2*)(sm + OFF_B1);

    int lane = t & 31;
    int wid  = t >> 5;
    // per-warp stage: SH (h, later r), SP0 (p0, later y1), SP1 (p1)
    float* SH  = sm + W_SMEM_FLOATS + wid * 768;
    float* SP0 = SH + 256;
    float* SP1 = SH + 512;

    const float2* h2v = (const float2*)g_h;
    const float2* t1v = (const float2*)g_t1;
    const float2* t2v = (const float2*)g_t2;
    const float2* t3v = (const float2*)g_t3;

    int gw = (blockIdx.x * blockDim.x + t) >> 5;
    int nw = (gridDim.x * blockDim.x) >> 5;
    const int NG = NN / 4;   // 25000, exact

    for (int g = gw; g < NG; g += nw) {
        int n0 = g * 4;
        float2 p0r[4], p1r[4];
#pragma unroll
        for (int i = 0; i < 4; i++) {
            size_t base = (size_t)(n0 + i) * 32 + lane;
            float2 h  = __ldg(&h2v[base]);
            float2 x1 = __ldg(&t1v[base]);
            float2 x2 = __ldg(&t2v[base]);
            float2 x3 = __ldg(&t3v[base]);
            float2 p0, p1;
            p0.x = fmaf(c00, h.x, fmaf(c01, x1.x, fmaf(c02, x2.x, c03 * x3.x)));
            p0.y = fmaf(c00, h.y, fmaf(c01, x1.y, fmaf(c02, x2.y, c03 * x3.y)));
            p1.x = fmaf(c10, h.x, fmaf(c11, x1.x, fmaf(c12, x2.x, c13 * x3.x)));
            p1.y = fmaf(c10, h.y, fmaf(c11, x1.y, fmaf(c12, x2.y, c13 * x3.y)));
            p0r[i] = p0; p1r[i] = p1;
            *(float2*)&SH [i * 64 + 2 * lane] = h;
            *(float2*)&SP0[i * 64 + 2 * lane] = p0;
            *(float2*)&SP1[i * 64 + 2 * lane] = p1;
        }
        __syncwarp();

        // merged matvecs: pp0 = Wb^T p0, pp1 = Wb^T p1, xp = Wx^T h
        float2 pp0[4], pp1[4], xp[4];
        {
            float2 bb = sbWb[lane], bx = sbWx[lane];
#pragma unroll
            for (int i = 0; i < 4; i++) { pp0[i] = bb; pp1[i] = bb; xp[i] = bx; }
        }
        for (int k4 = 0; k4 < 16; k4++) {
            float vh[4][4], vp0[4][4], vp1[4][4];
#pragma unroll
            for (int i = 0; i < 4; i++) {
                *(float4*)vh[i]  = *(const float4*)&SH [i * 64 + k4 * 4];
                *(float4*)vp0[i] = *(const float4*)&SP0[i * 64 + k4 * 4];
                *(float4*)vp1[i] = *(const float4*)&SP1[i * 64 + k4 * 4];
            }
#pragma unroll
            for (int kk = 0; kk < 4; kk++) {
                int k = k4 * 4 + kk;
                float2 wb_ = sWbv[k * 32 + lane];
                float2 wx_ = sWxv[k * 32 + lane];
#pragma unroll
                for (int i = 0; i < 4; i++) {
                    pp0[i].x = fmaf(vp0[i][kk], wb_.x, pp0[i].x);
                    pp0[i].y = fmaf(vp0[i][kk], wb_.y, pp0[i].y);
                    pp1[i].x = fmaf(vp1[i][kk], wb_.x, pp1[i].x);
                    pp1[i].y = fmaf(vp1[i][kk], wb_.y, pp1[i].y);
                    xp[i].x  = fmaf(vh[i][kk],  wx_.x, xp[i].x);
                    xp[i].y  = fmaf(vh[i][kk],  wx_.y, xp[i].y);
                }
            }
        }
        __syncwarp();

        // attention + combine; stage r into SH
        float2 vcl = svc[lane];
#pragma unroll
        for (int i = 0; i < 4; i++) {
            float s0 = warpsum(tanh_fast(pp0[i].x + xp[i].x) * vcl.x +
                               tanh_fast(pp0[i].y + xp[i].y) * vcl.y);
            float s1 = warpsum(tanh_fast(pp1[i].x + xp[i].x) * vcl.x +
                               tanh_fast(pp1[i].y + xp[i].y) * vcl.y);
            float m = fmaxf(s0, s1);
            float e0 = __expf(s0 - m), e1 = __expf(s1 - m);
            float inv = 1.f / (e0 + e1);
            float a0 = e0 * inv, a1 = e1 * inv;
            float2 r;
            r.x = a0 * p0r[i].x + a1 * p1r[i].x;
            r.y = a0 * p0r[i].y + a1 * p1r[i].y;
            *(float2*)&SH[i * 64 + 2 * lane] = r;
        }
        __syncwarp();

        // y1 = relu(W1^T r + b1); stage y1 into SP0
        float2 y1[4];
        {
            float2 b = sb1[lane];
#pragma unroll
            for (int i = 0; i < 4; i++) y1[i] = b;
        }
        for (int k4 = 0; k4 < 16; k4++) {
            float vr[4][4];
#pragma unroll
            for (int i = 0; i < 4; i++)
                *(float4*)vr[i] = *(const float4*)&SH[i * 64 + k4 * 4];
#pragma unroll
            for (int kk = 0; kk < 4; kk++) {
                int k = k4 * 4 + kk;
                float2 w1_ = sW1v[k * 32 + lane];
#pragma unroll
                for (int i = 0; i < 4; i++) {
                    y1[i].x = fmaf(vr[i][kk], w1_.x, y1[i].x);
                    y1[i].y = fmaf(vr[i][kk], w1_.y, y1[i].y);
                }
            }
        }
        __syncwarp();
#pragma unroll
        for (int i = 0; i < 4; i++) {
            y1[i].x = fmaxf(y1[i].x, 0.f);
            y1[i].y = fmaxf(y1[i].y, 0.f);
            *(float2*)&SP0[i * 64 + 2 * lane] = y1[i];
        }
        __syncwarp();

        // y2[c]=relu(W2^T y1 + b2), c = lane (32 outputs)
        float acc[4];
        {
            float b = sm[OFF_B2 + lane];
#pragma unroll
            for (int i = 0; i < 4; i++) acc[i] = b;
        }
        for (int k4 = 0; k4 < 16; k4++) {
            float vy[4][4];
#pragma unroll
            for (int i = 0; i < 4; i++)
                *(float4*)vy[i] = *(const float4*)&SP0[i * 64 + k4 * 4];
#pragma unroll
            for (int kk = 0; kk < 4; kk++) {
                int k = k4 * 4 + kk;
                float w2_ = sW2[k * 32 + lane];
#pragma unroll
                for (int i = 0; i < 4; i++)
                    acc[i] = fmaf(vy[i][kk], w2_, acc[i]);
            }
        }

        float w30 = sW3[lane * 2 + 0];
        float w31 = sW3[lane * 2 + 1];
        float ob0 = sm[OFF_B3 + 0], ob1 = sm[OFF_B3 + 1];
#pragma unroll
        for (int i = 0; i < 4; i++) {
            float y2 = fmaxf(acc[i], 0.f);
            float q0 = warpsum(y2 * w30);
            float q1 = warpsum(y2 * w31);
            if (lane == 0) {
                out[(size_t)(n0 + i) * 2 + 0] = ob0 + q0;
                out[(size_t)(n0 + i) * 2 + 1] = ob1 + q1;
            }
        }
    }
}

// ---------------- launch ----------------------------------------------------
extern "C" void kernel_launch(void* const* d_in, const int* in_sizes, int n_in,
                              void* d_out, int out_size) {
    const float* x      = (const float*)d_in[0];
    const void*  esrc   = d_in[1];
    const void*  edst   = d_in[2];
    const float* evals  = (const float*)d_in[3];
    const float* Win    = (const float*)d_in[4];
    const float* bin    = (const float*)d_in[5];
    const float* thetas = (const float*)d_in[6];
    const float* Wb     = (const float*)d_in[7];
    const float* bWb    = (const float*)d_in[8];
    const float* Wx     = (const float*)d_in[9];
    const float* bWx    = (const float*)d_in[10];
    const float* vc     = (const float*)d_in[11];
    const float* W1     = (const float*)d_in[12];
    const float* b1     = (const float*)d_in[13];
    const float* W2     = (const float*)d_in[14];
    const float* b2     = (const float*)d_in[15];
    const float* W3     = (const float*)d_in[16];
    const float* b3     = (const float*)d_in[17];
    float* out = (float*)d_out;

    cudaFuncSetAttribute(epilogue_kernel,
                         cudaFuncAttributeMaxDynamicSharedMemorySize,
                         EPI_SMEM_BYTES);

    detect_kernel<<<1, 32>>>((const unsigned int*)esrc);
    zero_cnt_kernel<<<(NN + 255) / 256, 256>>>();
    convert_hist_kernel<<<(EE + 255) / 256, 256>>>(esrc, edst);
    scan_block_kernel<<<NB_SCAN, 512>>>();
    scan_bsum_kernel<<<1, 256>>>();
    add_offsets_kernel<<<(NN + 255) / 256, 256>>>();
    scatter_kernel<<<(EE + 255) / 256, 256>>>(evals);

    gemm_in_kernel<<<1184, 256>>>(x, Win, bin);

    spmm_csr_kernel<0><<<1184, 256>>>();
    spmm_csr_kernel<1><<<1184, 256>>>();
    spmm_csr_kernel<2><<<1184, 256>>>();

    epilogue_kernel<<<296, 256, EPI_SMEM_BYTES>>>(
        thetas, Wb, bWb, Wx, bWx, vc, W1, b1, W2, b2, W3, b3, out);
}

// round 9
// speedup vs baseline: 1.4951x; 1.0917x over previous
#include <cuda_runtime.h>
#include <cuda_bf16.h>
#include <cstdint>

#define NN 100000
#define EE 1600000
#define CIN 128
#define CC 64
#define NB_SCAN 196   // ceil(NN/512)

// ---------------- scratch (device globals; no allocation allowed) ----------
__device__ float g_h [NN * CC];
__device__ float g_t1[NN * CC];
__device__ float g_t2[NN * CC];
__device__ float g_t3[NN * CC];
__device__ int   g_src[EE];
__device__ int   g_dst[EE];
__device__ int2  g_edge[EE];      // sorted-by-dst: {src, __float_as_int(val)}
__device__ int   g_rowptr[NN + 1];
__device__ int   g_cnt[NN];       // histogram, then running scatter offsets
__device__ int   g_bsum[NB_SCAN];
__device__ int   g_bsumex[NB_SCAN];
__device__ int   g_flag[1];

// ---------------- index width detection ------------------------------------
// int64 indices with values < 2^31: every odd 32-bit word is 0. 64 random
// int32 indices in [0,1e5) being all zero is impossible.
__global__ void detect_kernel(const unsigned int* p) {
    if (threadIdx.x == 0 && blockIdx.x == 0) {
        int is64 = 1;
        for (int i = 1; i < 128; i += 2)
            if (p[i] != 0u) { is64 = 0; break; }
        g_flag[0] = is64;
    }
}

__global__ void zero_cnt_kernel() {
    int i = blockIdx.x * blockDim.x + threadIdx.x;
    if (i < NN) g_cnt[i] = 0;
}

__global__ void convert_hist_kernel(const void* srcp, const void* dstp) {
    int e = blockIdx.x * blockDim.x + threadIdx.x;
    if (e >= EE) return;
    int s, d;
    if (g_flag[0]) {
        s = (int)((const long long*)srcp)[e];
        d = (int)((const long long*)dstp)[e];
    } else {
        s = ((const int*)srcp)[e];
        d = ((const int*)dstp)[e];
    }
    g_src[e] = s;
    g_dst[e] = d;
    atomicAdd(&g_cnt[d], 1);
}

// ---------------- 2-level exclusive scan over g_cnt ------------------------
__global__ void scan_block_kernel() {   // 512 threads per block
    __shared__ int s[512];
    int tid = threadIdx.x;
    int i = blockIdx.x * 512 + tid;
    int v = (i < NN) ? g_cnt[i] : 0;
    s[tid] = v;
    __syncthreads();
#pragma unroll
    for (int off = 1; off < 512; off <<= 1) {
        int t = (tid >= off) ? s[tid - off] : 0;
        __syncthreads();
        s[tid] += t;
        __syncthreads();
    }
    if (i < NN) g_rowptr[i] = s[tid] - v;
    if (tid == 511) g_bsum[blockIdx.x] = s[511];
}

__global__ void scan_bsum_kernel() {    // single block, 256 threads
    __shared__ int s[256];
    int tid = threadIdx.x;
    int v = (tid < NB_SCAN) ? g_bsum[tid] : 0;
    s[tid] = v;
    __syncthreads();
#pragma unroll
    for (int off = 1; off < 256; off <<= 1) {
        int t = (tid >= off) ? s[tid - off] : 0;
        __syncthreads();
        s[tid] += t;
        __syncthreads();
    }
    if (tid < NB_SCAN) g_bsumex[tid] = s[tid] - v;
}

__global__ void add_offsets_kernel() {
    int i = blockIdx.x * blockDim.x + threadIdx.x;
    if (i < NN) {
        int r = g_rowptr[i] + g_bsumex[i >> 9];
        g_rowptr[i] = r;
        g_cnt[i] = r;
    }
    if (i == 0) g_rowptr[NN] = EE;
}

__global__ void scatter_kernel(const float* __restrict__ vals) {
    int e = blockIdx.x * blockDim.x + threadIdx.x;
    if (e >= EE) return;
    int d = g_dst[e];
    int pos = atomicAdd(&g_cnt[d], 1);
    g_edge[pos] = make_int2(g_src[e], __float_as_int(vals[e]));
}

// ---------------- input GEMM: h = relu(x @ W_in + b_in) ---------------------
__global__ void gemm_in_kernel(const float* __restrict__ x,
                               const float* __restrict__ Win,
                               const float* __restrict__ bin) {
    __shared__ float2 Ws[CIN * 32];
    __shared__ float bs[CC];
    for (int i = threadIdx.x; i < CIN * 32; i += blockDim.x) {
        int k = i >> 5, l = i & 31;
        Ws[i] = make_float2(Win[k * CC + l], Win[k * CC + l + 32]);
    }
    if (threadIdx.x < CC) bs[threadIdx.x] = bin[threadIdx.x];
    __syncthreads();

    int lane = threadIdx.x & 31;
    int gw = (blockIdx.x * blockDim.x + threadIdx.x) >> 5;
    int nw = (gridDim.x * blockDim.x) >> 5;
    const int NG = NN / 4;   // 25000, exact

    for (int g = gw; g < NG; g += nw) {
        int n0 = g * 4;
        const float4* xr0 = (const float4*)(x + (size_t)(n0 + 0) * CIN);
        const float4* xr1 = (const float4*)(x + (size_t)(n0 + 1) * CIN);
        const float4* xr2 = (const float4*)(x + (size_t)(n0 + 2) * CIN);
        const float4* xr3 = (const float4*)(x + (size_t)(n0 + 3) * CIN);
        float b0 = bs[lane], b1 = bs[lane + 32];
        float a00 = b0, a01 = b1, a10 = b0, a11 = b1;
        float a20 = b0, a21 = b1, a30 = b0, a31 = b1;
#pragma unroll 4
        for (int k4 = 0; k4 < CIN / 4; k4++) {
            float xa[4], xb[4], xc[4], xd[4];
            *(float4*)xa = __ldg(&xr0[k4]);
            *(float4*)xb = __ldg(&xr1[k4]);
            *(float4*)xc = __ldg(&xr2[k4]);
            *(float4*)xd = __ldg(&xr3[k4]);
#pragma unroll
            for (int kk = 0; kk < 4; kk++) {
                float2 w = Ws[(k4 * 4 + kk) * 32 + lane];
                a00 = fmaf(xa[kk], w.x, a00); a01 = fmaf(xa[kk], w.y, a01);
                a10 = fmaf(xb[kk], w.x, a10); a11 = fmaf(xb[kk], w.y, a11);
                a20 = fmaf(xc[kk], w.x, a20); a21 = fmaf(xc[kk], w.y, a21);
                a30 = fmaf(xd[kk], w.x, a30); a31 = fmaf(xd[kk], w.y, a31);
            }
        }
        g_h[(size_t)(n0 + 0) * CC + lane]      = fmaxf(a00, 0.f);
        g_h[(size_t)(n0 + 0) * CC + lane + 32] = fmaxf(a01, 0.f);
        g_h[(size_t)(n0 + 1) * CC + lane]      = fmaxf(a10, 0.f);
        g_h[(size_t)(n0 + 1) * CC + lane + 32] = fmaxf(a11, 0.f);
        g_h[(size_t)(n0 + 2) * CC + lane]      = fmaxf(a20, 0.f);
        g_h[(size_t)(n0 + 2) * CC + lane + 32] = fmaxf(a21, 0.f);
        g_h[(size_t)(n0 + 3) * CC + lane]      = fmaxf(a30, 0.f);
        g_h[(size_t)(n0 + 3) * CC + lane + 32] = fmaxf(a31, 0.f);
    }
}

// ---------------- CSR SpMM: split-row float4 gather --------------------------
// One warp per dst row. 16 lanes own the 64 channels as float4; the two warp
// halves gather TWO different edges' source rows per LDG.128. Final combine is
// 4 shfl_xor(16). 8-edge main loop → 4 row-gathers in flight per warp.
template <int S>
__global__ void spmm_csr_kernel() {
    const float4* __restrict__ in =
        (const float4*)((S == 0) ? g_h : (S == 1) ? g_t1 : g_t2);
    float4* __restrict__ out =
        (float4*)((S == 0) ? g_t1 : (S == 1) ? g_t2 : g_t3);

    int lane = threadIdx.x & 31;
    int half = lane >> 4;          // 0 or 1
    int li   = lane & 15;          // channel quad
    int gw = (blockIdx.x * blockDim.x + threadIdx.x) >> 5;
    int nw = (gridDim.x * blockDim.x) >> 5;

    for (int n = gw; n < NN; n += nw) {
        int beg = g_rowptr[n];
        int end = g_rowptr[n + 1];
        float4 a = make_float4(0.f, 0.f, 0.f, 0.f);
        int j = beg;
        for (; j + 7 < end; j += 8) {
            int2 e0 = __ldg(&g_edge[j + 0 + half]);
            int2 e1 = __ldg(&g_edge[j + 2 + half]);
            int2 e2 = __ldg(&g_edge[j + 4 + half]);
            int2 e3 = __ldg(&g_edge[j + 6 + half]);
            float4 u0 = __ldg(&in[(size_t)e0.x * 16 + li]);
            float4 u1 = __ldg(&in[(size_t)e1.x * 16 + li]);
            float4 u2 = __ldg(&in[(size_t)e2.x * 16 + li]);
            float4 u3 = __ldg(&in[(size_t)e3.x * 16 + li]);
            float v0 = __int_as_float(e0.y);
            float v1 = __int_as_float(e1.y);
            float v2 = __int_as_float(e2.y);
            float v3 = __int_as_float(e3.y);
            a.x = fmaf(v0, u0.x, a.x); a.y = fmaf(v0, u0.y, a.y);
            a.z = fmaf(v0, u0.z, a.z); a.w = fmaf(v0, u0.w, a.w);
            a.x = fmaf(v1, u1.x, a.x); a.y = fmaf(v1, u1.y, a.y);
            a.z = fmaf(v1, u1.z, a.z); a.w = fmaf(v1, u1.w, a.w);
            a.x = fmaf(v2, u2.x, a.x); a.y = fmaf(v2, u2.y, a.y);
            a.z = fmaf(v2, u2.z, a.z); a.w = fmaf(v2, u2.w, a.w);
            a.x = fmaf(v3, u3.x, a.x); a.y = fmaf(v3, u3.y, a.y);
            a.z = fmaf(v3, u3.z, a.z); a.w = fmaf(v3, u3.w, a.w);
        }
        for (; j + 1 < end; j += 2) {
            int2 e0 = __ldg(&g_edge[j + half]);
            float4 u0 = __ldg(&in[(size_t)e0.x * 16 + li]);
            float v0 = __int_as_float(e0.y);
            a.x = fmaf(v0, u0.x, a.x); a.y = fmaf(v0, u0.y, a.y);
            a.z = fmaf(v0, u0.z, a.z); a.w = fmaf(v0, u0.w, a.w);
        }
        if (j < end && half == 0) {
            int2 e0 = __ldg(&g_edge[j]);
            float4 u0 = __ldg(&in[(size_t)e0.x * 16 + li]);
            float v0 = __int_as_float(e0.y);
            a.x = fmaf(v0, u0.x, a.x); a.y = fmaf(v0, u0.y, a.y);
            a.z = fmaf(v0, u0.z, a.z); a.w = fmaf(v0, u0.w, a.w);
        }
        a.x += __shfl_xor_sync(0xffffffffu, a.x, 16);
        a.y += __shfl_xor_sync(0xffffffffu, a.y, 16);
        a.z += __shfl_xor_sync(0xffffffffu, a.z, 16);
        a.w += __shfl_xor_sync(0xffffffffu, a.w, 16);
        if (half == 0)
            out[(size_t)n * 16 + li] = a;
    }
}

// ---------------- fused epilogue: 4 nodes/warp, smem-staged vectors ---------
__device__ __forceinline__ float tanh_fast(float x) {
    float y;
    asm("tanh.approx.f32 %0, %1;" : "=f"(y) : "f"(x));
    return y;
}

__device__ __forceinline__ float warpsum(float v) {
    v += __shfl_xor_sync(0xffffffffu, v, 16);
    v += __shfl_xor_sync(0xffffffffu, v, 8);
    v += __shfl_xor_sync(0xffffffffu, v, 4);
    v += __shfl_xor_sync(0xffffffffu, v, 2);
    v += __shfl_xor_sync(0xffffffffu, v, 1);
    return v;
}

#define OFF_WB  0
#define OFF_WX  4096
#define OFF_W1  8192
#define OFF_W2  12288
#define OFF_W3  14336
#define OFF_VC  14400
#define OFF_BWB 14464
#define OFF_BWX 14528
#define OFF_B1  14592
#define OFF_B2  14656
#define OFF_B3  14688
#define W_SMEM_FLOATS 14720
#define EPI_WARPS 8
#define STAGE_FLOATS (EPI_WARPS * 768)     // 3 vecs x 4 nodes x 64 per warp
#define EPI_SMEM_BYTES ((W_SMEM_FLOATS + STAGE_FLOATS) * 4)

__global__ __launch_bounds__(256, 2)
void epilogue_kernel(const float* __restrict__ thetas,
                     const float* __restrict__ Wb, const float* __restrict__ bWb,
                     const float* __restrict__ Wx, const float* __restrict__ bWx,
                     const float* __restrict__ vc,
                     const float* __restrict__ W1, const float* __restrict__ b1,
                     const float* __restrict__ W2, const float* __restrict__ b2,
                     const float* __restrict__ W3, const float* __restrict__ b3,
                     float* __restrict__ out) {
    extern __shared__ float sm[];
    int t = threadIdx.x;
    for (int i = t; i < 4096; i += blockDim.x) {
        sm[OFF_WB + i] = Wb[i];
        sm[OFF_WX + i] = Wx[i];
        sm[OFF_W1 + i] = W1[i];
    }
    for (int i = t; i < 2048; i += blockDim.x) sm[OFF_W2 + i] = W2[i];
    if (t < 64) {
        sm[OFF_W3 + t]  = W3[t];
        sm[OFF_VC + t]  = vc[t];
        sm[OFF_BWB + t] = bWb[t];
        sm[OFF_BWX + t] = bWx[t];
        sm[OFF_B1 + t]  = b1[t];
    }
    if (t < 32) sm[OFF_B2 + t] = b2[t];
    if (t < 2)  sm[OFF_B3 + t] = b3[t];
    __syncthreads();

    float t00 = thetas[0], t01 = thetas[1], t02 = thetas[2], t03 = thetas[3];
    float t10 = thetas[4], t11 = thetas[5], t12 = thetas[6], t13 = thetas[7];
    float c00 = t00;
    float c01 = -3.f * t00 + 3.f * t01;
    float c02 =  3.f * t00 - 6.f * t01 + 3.f * t02;
    float c03 = -1.f * t00 + 3.f * t01 - 3.f * t02 + t03;
    float c10 = t10;
    float c11 = -3.f * t10 + 3.f * t11;
    float c12 =  3.f * t10 - 6.f * t11 + 3.f * t12;
    float c13 = -1.f * t10 + 3.f * t11 - 3.f * t12 + t13;

    const float2* sWbv = (const float2*)(sm + OFF_WB);
    const float2* sWxv = (const float2*)(sm + OFF_WX);
    const float2* sW1v = (const float2*)(sm + OFF_W1);
    const float*  sW2  = sm + OFF_W2;
    const float*  sW3  = sm + OFF_W3;
    const float2* svc  = (const float2*)(sm + OFF_VC);
    const float2* sbWb = (const float2*)(sm + OFF_BWB);
    const float2* sbWx = (const float2*)(sm + OFF_BWX);
    const float2* sb1  = (const float2*)(sm + OFF_B1);

    int lane = t & 31;
    int wid  = t >> 5;
    // per-warp stage: SH (h, later r), SP0 (p0, later y1), SP1 (p1)
    float* SH  = sm + W_SMEM_FLOATS + wid * 768;
    float* SP0 = SH + 256;
    float* SP1 = SH + 512;

    const float2* h2v = (const float2*)g_h;
    const float2* t1v = (const float2*)g_t1;
    const float2* t2v = (const float2*)g_t2;
    const float2* t3v = (const float2*)g_t3;

    int gw = (blockIdx.x * blockDim.x + t) >> 5;
    int nw = (gridDim.x * blockDim.x) >> 5;
    const int NG = NN / 4;   // 25000, exact

    for (int g = gw; g < NG; g += nw) {
        int n0 = g * 4;
        float2 p0r[4], p1r[4];
#pragma unroll
        for (int i = 0; i < 4; i++) {
            size_t base = (size_t)(n0 + i) * 32 + lane;
            float2 h  = __ldg(&h2v[base]);
            float2 x1 = __ldg(&t1v[base]);
            float2 x2 = __ldg(&t2v[base]);
            float2 x3 = __ldg(&t3v[base]);
            float2 p0, p1;
            p0.x = fmaf(c00, h.x, fmaf(c01, x1.x, fmaf(c02, x2.x, c03 * x3.x)));
            p0.y = fmaf(c00, h.y, fmaf(c01, x1.y, fmaf(c02, x2.y, c03 * x3.y)));
            p1.x = fmaf(c10, h.x, fmaf(c11, x1.x, fmaf(c12, x2.x, c13 * x3.x)));
            p1.y = fmaf(c10, h.y, fmaf(c11, x1.y, fmaf(c12, x2.y, c13 * x3.y)));
            p0r[i] = p0; p1r[i] = p1;
            *(float2*)&SH [i * 64 + 2 * lane] = h;
            *(float2*)&SP0[i * 64 + 2 * lane] = p0;
            *(float2*)&SP1[i * 64 + 2 * lane] = p1;
        }
        __syncwarp();

        // merged matvecs: pp0 = Wb^T p0, pp1 = Wb^T p1, xp = Wx^T h
        float2 pp0[4], pp1[4], xp[4];
        {
            float2 bb = sbWb[lane], bx = sbWx[lane];
#pragma unroll
            for (int i = 0; i < 4; i++) { pp0[i] = bb; pp1[i] = bb; xp[i] = bx; }
        }
        for (int k4 = 0; k4 < 16; k4++) {
            float vh[4][4], vp0[4][4], vp1[4][4];
#pragma unroll
            for (int i = 0; i < 4; i++) {
                *(float4*)vh[i]  = *(const float4*)&SH [i * 64 + k4 * 4];
                *(float4*)vp0[i] = *(const float4*)&SP0[i * 64 + k4 * 4];
                *(float4*)vp1[i] = *(const float4*)&SP1[i * 64 + k4 * 4];
            }
#pragma unroll
            for (int kk = 0; kk < 4; kk++) {
                int k = k4 * 4 + kk;
                float2 wb_ = sWbv[k * 32 + lane];
                float2 wx_ = sWxv[k * 32 + lane];
#pragma unroll
                for (int i = 0; i < 4; i++) {
                    pp0[i].x = fmaf(vp0[i][kk], wb_.x, pp0[i].x);
                    pp0[i].y = fmaf(vp0[i][kk], wb_.y, pp0[i].y);
                    pp1[i].x = fmaf(vp1[i][kk], wb_.x, pp1[i].x);
                    pp1[i].y = fmaf(vp1[i][kk], wb_.y, pp1[i].y);
                    xp[i].x  = fmaf(vh[i][kk],  wx_.x, xp[i].x);
                    xp[i].y  = fmaf(vh[i][kk],  wx_.y, xp[i].y);
                }
            }
        }
        __syncwarp();

        // attention + combine; stage r into SH
        float2 vcl = svc[lane];
#pragma unroll
        for (int i = 0; i < 4; i++) {
            float s0 = warpsum(tanh_fast(pp0[i].x + xp[i].x) * vcl.x +
                               tanh_fast(pp0[i].y + xp[i].y) * vcl.y);
            float s1 = warpsum(tanh_fast(pp1[i].x + xp[i].x) * vcl.x +
                               tanh_fast(pp1[i].y + xp[i].y) * vcl.y);
            float m = fmaxf(s0, s1);
            float e0 = __expf(s0 - m), e1 = __expf(s1 - m);
            float inv = 1.f / (e0 + e1);
            float a0 = e0 * inv, a1 = e1 * inv;
            float2 r;
            r.x = a0 * p0r[i].x + a1 * p1r[i].x;
            r.y = a0 * p0r[i].y + a1 * p1r[i].y;
            *(float2*)&SH[i * 64 + 2 * lane] = r;
        }
        __syncwarp();

        // y1 = relu(W1^T r + b1); stage y1 into SP0
        float2 y1[4];
        {
            float2 b = sb1[lane];
#pragma unroll
            for (int i = 0; i < 4; i++) y1[i] = b;
        }
        for (int k4 = 0; k4 < 16; k4++) {
            float vr[4][4];
#pragma unroll
            for (int i = 0; i < 4; i++)
                *(float4*)vr[i] = *(const float4*)&SH[i * 64 + k4 * 4];
#pragma unroll
            for (int kk = 0; kk < 4; kk++) {
                int k = k4 * 4 + kk;
                float2 w1_ = sW1v[k * 32 + lane];
#pragma unroll
                for (int i = 0; i < 4; i++) {
                    y1[i].x = fmaf(vr[i][kk], w1_.x, y1[i].x);
                    y1[i].y = fmaf(vr[i][kk], w1_.y, y1[i].y);
                }
            }
        }
        __syncwarp();
#pragma unroll
        for (int i = 0; i < 4; i++) {
            y1[i].x = fmaxf(y1[i].x, 0.f);
            y1[i].y = fmaxf(y1[i].y, 0.f);
            *(float2*)&SP0[i * 64 + 2 * lane] = y1[i];
        }
        __syncwarp();

        // y2[c]=relu(W2^T y1 + b2), c = lane (32 outputs)
        float acc[4];
        {
            float b = sm[OFF_B2 + lane];
#pragma unroll
            for (int i = 0; i < 4; i++) acc[i] = b;
        }
        for (int k4 = 0; k4 < 16; k4++) {
            float vy[4][4];
#pragma unroll
            for (int i = 0; i < 4; i++)
                *(float4*)vy[i] = *(const float4*)&SP0[i * 64 + k4 * 4];
#pragma unroll
            for (int kk = 0; kk < 4; kk++) {
                int k = k4 * 4 + kk;
                float w2_ = sW2[k * 32 + lane];
#pragma unroll
                for (int i = 0; i < 4; i++)
                    acc[i] = fmaf(vy[i][kk], w2_, acc[i]);
            }
        }

        float w30 = sW3[lane * 2 + 0];
        float w31 = sW3[lane * 2 + 1];
        float ob0 = sm[OFF_B3 + 0], ob1 = sm[OFF_B3 + 1];
#pragma unroll
        for (int i = 0; i < 4; i++) {
            float y2 = fmaxf(acc[i], 0.f);
            float q0 = warpsum(y2 * w30);
            float q1 = warpsum(y2 * w31);
            if (lane == 0) {
                out[(size_t)(n0 + i) * 2 + 0] = ob0 + q0;
                out[(size_t)(n0 + i) * 2 + 1] = ob1 + q1;
            }
        }
    }
}

// ---------------- launch ----------------------------------------------------
extern "C" void kernel_launch(void* const* d_in, const int* in_sizes, int n_in,
                              void* d_out, int out_size) {
    const float* x      = (const float*)d_in[0];
    const void*  esrc   = d_in[1];
    const void*  edst   = d_in[2];
    const float* evals  = (const float*)d_in[3];
    const float* Win    = (const float*)d_in[4];
    const float* bin    = (const float*)d_in[5];
    const float* thetas = (const float*)d_in[6];
    const float* Wb     = (const float*)d_in[7];
    const float* bWb    = (const float*)d_in[8];
    const float* Wx     = (const float*)d_in[9];
    const float* bWx    = (const float*)d_in[10];
    const float* vc     = (const float*)d_in[11];
    const float* W1     = (const float*)d_in[12];
    const float* b1     = (const float*)d_in[13];
    const float* W2     = (const float*)d_in[14];
    const float* b2     = (const float*)d_in[15];
    const float* W3     = (const float*)d_in[16];
    const float* b3     = (const float*)d_in[17];
    float* out = (float*)d_out;

    // one-time resources (host-side only; no device memory)
    static cudaStream_t s2 = nullptr;
    static cudaEvent_t evFork = nullptr, evJoin = nullptr;
    if (s2 == nullptr) {
        cudaStreamCreateWithFlags(&s2, cudaStreamNonBlocking);
        cudaEventCreateWithFlags(&evFork, cudaEventDisableTiming);
        cudaEventCreateWithFlags(&evJoin, cudaEventDisableTiming);
        cudaFuncSetAttribute(epilogue_kernel,
                             cudaFuncAttributeMaxDynamicSharedMemorySize,
                             EPI_SMEM_BYTES);
    }

    // fork: CSR build on s2, gemm_in on the main (capture) stream
    cudaEventRecord(evFork, 0);
    cudaStreamWaitEvent(s2, evFork, 0);

    detect_kernel<<<1, 32, 0, s2>>>((const unsigned int*)esrc);
    zero_cnt_kernel<<<(NN + 255) / 256, 256, 0, s2>>>();
    convert_hist_kernel<<<(EE + 255) / 256, 256, 0, s2>>>(esrc, edst);
    scan_block_kernel<<<NB_SCAN, 512, 0, s2>>>();
    scan_bsum_kernel<<<1, 256, 0, s2>>>();
    add_offsets_kernel<<<(NN + 255) / 256, 256, 0, s2>>>();
    scatter_kernel<<<(EE + 255) / 256, 256, 0, s2>>>(evals);
    cudaEventRecord(evJoin, s2);

    gemm_in_kernel<<<1184, 256>>>(x, Win, bin);

    // join: SpMM needs both h and the CSR structure
    cudaStreamWaitEvent(0, evJoin, 0);

    spmm_csr_kernel<0><<<1184, 256>>>();
    spmm_csr_kernel<1><<<1184, 256>>>();
    spmm_csr_kernel<2><<<1184, 256>>>();

    epilogue_kernel<<<296, 256, EPI_SMEM_BYTES>>>(
        thetas, Wb, bWb, Wx, bWx, vc, W1, b1, W2, b2, W3, b3, out);
}

// round 10
// speedup vs baseline: 1.4961x; 1.0006x over previous
#include <cuda_runtime.h>
#include <cuda_bf16.h>
#include <cstdint>

#define NN 100000
#define EE 1600000
#define CIN 128
#define CC 64
#define NB_SCAN 196   // ceil(NN/512)

// ---------------- scratch (device globals; no allocation allowed) ----------
__device__ float g_h [NN * CC];
__device__ float g_t1[NN * CC];
__device__ float g_t2[NN * CC];
__device__ float g_t3[NN * CC];
__device__ int   g_src[EE];
__device__ int   g_dst[EE];
__device__ int2  g_edge[EE];      // sorted-by-dst: {src, __float_as_int(val)}
__device__ int   g_rowptr[NN + 1];
__device__ int   g_cnt[NN];       // histogram, then running scatter offsets
__device__ int   g_bsum[NB_SCAN];
__device__ int   g_bsumex[NB_SCAN];
__device__ int   g_flag[1];

// ---------------- index width detection ------------------------------------
// int64 indices with values < 2^31: every odd 32-bit word is 0. 64 random
// int32 indices in [0,1e5) being all zero is impossible.
__global__ void detect_kernel(const unsigned int* p) {
    if (threadIdx.x == 0 && blockIdx.x == 0) {
        int is64 = 1;
        for (int i = 1; i < 128; i += 2)
            if (p[i] != 0u) { is64 = 0; break; }
        g_flag[0] = is64;
    }
}

__global__ void zero_cnt_kernel() {
    int i = blockIdx.x * blockDim.x + threadIdx.x;
    if (i < NN) g_cnt[i] = 0;
}

__global__ void convert_hist_kernel(const void* srcp, const void* dstp) {
    int e = blockIdx.x * blockDim.x + threadIdx.x;
    if (e >= EE) return;
    int s, d;
    if (g_flag[0]) {
        s = (int)((const long long*)srcp)[e];
        d = (int)((const long long*)dstp)[e];
    } else {
        s = ((const int*)srcp)[e];
        d = ((const int*)dstp)[e];
    }
    g_src[e] = s;
    g_dst[e] = d;
    atomicAdd(&g_cnt[d], 1);
}

// ---------------- 2-level exclusive scan over g_cnt ------------------------
__global__ void scan_block_kernel() {   // 512 threads per block
    __shared__ int s[512];
    int tid = threadIdx.x;
    int i = blockIdx.x * 512 + tid;
    int v = (i < NN) ? g_cnt[i] : 0;
    s[tid] = v;
    __syncthreads();
#pragma unroll
    for (int off = 1; off < 512; off <<= 1) {
        int t = (tid >= off) ? s[tid - off] : 0;
        __syncthreads();
        s[tid] += t;
        __syncthreads();
    }
    if (i < NN) g_rowptr[i] = s[tid] - v;
    if (tid == 511) g_bsum[blockIdx.x] = s[511];
}

__global__ void scan_bsum_kernel() {    // single block, 256 threads
    __shared__ int s[256];
    int tid = threadIdx.x;
    int v = (tid < NB_SCAN) ? g_bsum[tid] : 0;
    s[tid] = v;
    __syncthreads();
#pragma unroll
    for (int off = 1; off < 256; off <<= 1) {
        int t = (tid >= off) ? s[tid - off] : 0;
        __syncthreads();
        s[tid] += t;
        __syncthreads();
    }
    if (tid < NB_SCAN) g_bsumex[tid] = s[tid] - v;
}

__global__ void add_offsets_kernel() {
    int i = blockIdx.x * blockDim.x + threadIdx.x;
    if (i < NN) {
        int r = g_rowptr[i] + g_bsumex[i >> 9];
        g_rowptr[i] = r;
        g_cnt[i] = r;
    }
    if (i == 0) g_rowptr[NN] = EE;
}

__global__ void scatter_kernel(const float* __restrict__ vals) {
    int e = blockIdx.x * blockDim.x + threadIdx.x;
    if (e >= EE) return;
    int d = g_dst[e];
    int pos = atomicAdd(&g_cnt[d], 1);
    g_edge[pos] = make_int2(g_src[e], __float_as_int(vals[e]));
}

// ---------------- input GEMM: h = relu(x @ W_in + b_in) ---------------------
__global__ void gemm_in_kernel(const float* __restrict__ x,
                               const float* __restrict__ Win,
                               const float* __restrict__ bin) {
    __shared__ float2 Ws[CIN * 32];
    __shared__ float bs[CC];
    for (int i = threadIdx.x; i < CIN * 32; i += blockDim.x) {
        int k = i >> 5, l = i & 31;
        Ws[i] = make_float2(Win[k * CC + l], Win[k * CC + l + 32]);
    }
    if (threadIdx.x < CC) bs[threadIdx.x] = bin[threadIdx.x];
    __syncthreads();

    int lane = threadIdx.x & 31;
    int gw = (blockIdx.x * blockDim.x + threadIdx.x) >> 5;
    int nw = (gridDim.x * blockDim.x) >> 5;
    const int NG = NN / 4;   // 25000, exact

    for (int g = gw; g < NG; g += nw) {
        int n0 = g * 4;
        const float4* xr0 = (const float4*)(x + (size_t)(n0 + 0) * CIN);
        const float4* xr1 = (const float4*)(x + (size_t)(n0 + 1) * CIN);
        const float4* xr2 = (const float4*)(x + (size_t)(n0 + 2) * CIN);
        const float4* xr3 = (const float4*)(x + (size_t)(n0 + 3) * CIN);
        float b0 = bs[lane], b1 = bs[lane + 32];
        float a00 = b0, a01 = b1, a10 = b0, a11 = b1;
        float a20 = b0, a21 = b1, a30 = b0, a31 = b1;
#pragma unroll 4
        for (int k4 = 0; k4 < CIN / 4; k4++) {
            float xa[4], xb[4], xc[4], xd[4];
            *(float4*)xa = __ldg(&xr0[k4]);
            *(float4*)xb = __ldg(&xr1[k4]);
            *(float4*)xc = __ldg(&xr2[k4]);
            *(float4*)xd = __ldg(&xr3[k4]);
#pragma unroll
            for (int kk = 0; kk < 4; kk++) {
                float2 w = Ws[(k4 * 4 + kk) * 32 + lane];
                a00 = fmaf(xa[kk], w.x, a00); a01 = fmaf(xa[kk], w.y, a01);
                a10 = fmaf(xb[kk], w.x, a10); a11 = fmaf(xb[kk], w.y, a11);
                a20 = fmaf(xc[kk], w.x, a20); a21 = fmaf(xc[kk], w.y, a21);
                a30 = fmaf(xd[kk], w.x, a30); a31 = fmaf(xd[kk], w.y, a31);
            }
        }
        g_h[(size_t)(n0 + 0) * CC + lane]      = fmaxf(a00, 0.f);
        g_h[(size_t)(n0 + 0) * CC + lane + 32] = fmaxf(a01, 0.f);
        g_h[(size_t)(n0 + 1) * CC + lane]      = fmaxf(a10, 0.f);
        g_h[(size_t)(n0 + 1) * CC + lane + 32] = fmaxf(a11, 0.f);
        g_h[(size_t)(n0 + 2) * CC + lane]      = fmaxf(a20, 0.f);
        g_h[(size_t)(n0 + 2) * CC + lane + 32] = fmaxf(a21, 0.f);
        g_h[(size_t)(n0 + 3) * CC + lane]      = fmaxf(a30, 0.f);
        g_h[(size_t)(n0 + 3) * CC + lane + 32] = fmaxf(a31, 0.f);
    }
}

// ---------------- CSR SpMM: split-row float4 gather --------------------------
// One warp per dst row. 16 lanes own the 64 channels as float4; the two warp
// halves gather TWO different edges' source rows per LDG.128. Final combine is
// 4 shfl_xor(16). 8-edge main loop → 4 row-gathers in flight per warp.
template <int S>
__global__ void spmm_csr_kernel() {
    const float4* __restrict__ in =
        (const float4*)((S == 0) ? g_h : (S == 1) ? g_t1 : g_t2);
    float4* __restrict__ out =
        (float4*)((S == 0) ? g_t1 : (S == 1) ? g_t2 : g_t3);

    int lane = threadIdx.x & 31;
    int half = lane >> 4;          // 0 or 1
    int li   = lane & 15;          // channel quad
    int gw = (blockIdx.x * blockDim.x + threadIdx.x) >> 5;
    int nw = (gridDim.x * blockDim.x) >> 5;

    for (int n = gw; n < NN; n += nw) {
        int beg = g_rowptr[n];
        int end = g_rowptr[n + 1];
        float4 a = make_float4(0.f, 0.f, 0.f, 0.f);
        int j = beg;
        for (; j + 7 < end; j += 8) {
            int2 e0 = __ldg(&g_edge[j + 0 + half]);
            int2 e1 = __ldg(&g_edge[j + 2 + half]);
            int2 e2 = __ldg(&g_edge[j + 4 + half]);
            int2 e3 = __ldg(&g_edge[j + 6 + half]);
            float4 u0 = __ldg(&in[(size_t)e0.x * 16 + li]);
            float4 u1 = __ldg(&in[(size_t)e1.x * 16 + li]);
            float4 u2 = __ldg(&in[(size_t)e2.x * 16 + li]);
            float4 u3 = __ldg(&in[(size_t)e3.x * 16 + li]);
            float v0 = __int_as_float(e0.y);
            float v1 = __int_as_float(e1.y);
            float v2 = __int_as_float(e2.y);
            float v3 = __int_as_float(e3.y);
            a.x = fmaf(v0, u0.x, a.x); a.y = fmaf(v0, u0.y, a.y);
            a.z = fmaf(v0, u0.z, a.z); a.w = fmaf(v0, u0.w, a.w);
            a.x = fmaf(v1, u1.x, a.x); a.y = fmaf(v1, u1.y, a.y);
            a.z = fmaf(v1, u1.z, a.z); a.w = fmaf(v1, u1.w, a.w);
            a.x = fmaf(v2, u2.x, a.x); a.y = fmaf(v2, u2.y, a.y);
            a.z = fmaf(v2, u2.z, a.z); a.w = fmaf(v2, u2.w, a.w);
            a.x = fmaf(v3, u3.x, a.x); a.y = fmaf(v3, u3.y, a.y);
            a.z = fmaf(v3, u3.z, a.z); a.w = fmaf(v3, u3.w, a.w);
        }
        for (; j + 1 < end; j += 2) {
            int2 e0 = __ldg(&g_edge[j + half]);
            float4 u0 = __ldg(&in[(size_t)e0.x * 16 + li]);
            float v0 = __int_as_float(e0.y);
            a.x = fmaf(v0, u0.x, a.x); a.y = fmaf(v0, u0.y, a.y);
            a.z = fmaf(v0, u0.z, a.z); a.w = fmaf(v0, u0.w, a.w);
        }
        if (j < end && half == 0) {
            int2 e0 = __ldg(&g_edge[j]);
            float4 u0 = __ldg(&in[(size_t)e0.x * 16 + li]);
            float v0 = __int_as_float(e0.y);
            a.x = fmaf(v0, u0.x, a.x); a.y = fmaf(v0, u0.y, a.y);
            a.z = fmaf(v0, u0.z, a.z); a.w = fmaf(v0, u0.w, a.w);
        }
        a.x += __shfl_xor_sync(0xffffffffu, a.x, 16);
        a.y += __shfl_xor_sync(0xffffffffu, a.y, 16);
        a.z += __shfl_xor_sync(0xffffffffu, a.z, 16);
        a.w += __shfl_xor_sync(0xffffffffu, a.w, 16);
        if (half == 0)
            out[(size_t)n * 16 + li] = a;
    }
}

// ---------------- fused epilogue: 4 nodes/warp, smem-staged vectors ---------
__device__ __forceinline__ float tanh_fast(float x) {
    float y;
    asm("tanh.approx.f32 %0, %1;" : "=f"(y) : "f"(x));
    return y;
}

__device__ __forceinline__ float warpsum(float v) {
    v += __shfl_xor_sync(0xffffffffu, v, 16);
    v += __shfl_xor_sync(0xffffffffu, v, 8);
    v += __shfl_xor_sync(0xffffffffu, v, 4);
    v += __shfl_xor_sync(0xffffffffu, v, 2);
    v += __shfl_xor_sync(0xffffffffu, v, 1);
    return v;
}

#define OFF_WB  0
#define OFF_WX  4096
#define OFF_W1  8192
#define OFF_W2  12288
#define OFF_W3  14336
#define OFF_VC  14400
#define OFF_BWB 14464
#define OFF_BWX 14528
#define OFF_B1  14592
#define OFF_B2  14656
#define OFF_B3  14688
#define W_SMEM_FLOATS 14720
#define EPI_WARPS 8
#define STAGE_FLOATS (EPI_WARPS * 768)     // 3 vecs x 4 nodes x 64 per warp
#define EPI_SMEM_BYTES ((W_SMEM_FLOATS + STAGE_FLOATS) * 4)

__global__ __launch_bounds__(256, 2)
void epilogue_kernel(const float* __restrict__ thetas,
                     const float* __restrict__ Wb, const float* __restrict__ bWb,
                     const float* __restrict__ Wx, const float* __restrict__ bWx,
                     const float* __restrict__ vc,
                     const float* __restrict__ W1, const float* __restrict__ b1,
                     const float* __restrict__ W2, const float* __restrict__ b2,
                     const float* __restrict__ W3, const float* __restrict__ b3,
                     float* __restrict__ out) {
    extern __shared__ float sm[];
    int t = threadIdx.x;
    for (int i = t; i < 4096; i += blockDim.x) {
        sm[OFF_WB + i] = Wb[i];
        sm[OFF_WX + i] = Wx[i];
        sm[OFF_W1 + i] = W1[i];
    }
    for (int i = t; i < 2048; i += blockDim.x) sm[OFF_W2 + i] = W2[i];
    if (t < 64) {
        sm[OFF_W3 + t]  = W3[t];
        sm[OFF_VC + t]  = vc[t];
        sm[OFF_BWB + t] = bWb[t];
        sm[OFF_BWX + t] = bWx[t];
        sm[OFF_B1 + t]  = b1[t];
    }
    if (t < 32) sm[OFF_B2 + t] = b2[t];
    if (t < 2)  sm[OFF_B3 + t] = b3[t];
    __syncthreads();

    float t00 = thetas[0], t01 = thetas[1], t02 = thetas[2], t03 = thetas[3];
    float t10 = thetas[4], t11 = thetas[5], t12 = thetas[6], t13 = thetas[7];
    float c00 = t00;
    float c01 = -3.f * t00 + 3.f * t01;
    float c02 =  3.f * t00 - 6.f * t01 + 3.f * t02;
    float c03 = -1.f * t00 + 3.f * t01 - 3.f * t02 + t03;
    float c10 = t10;
    float c11 = -3.f * t10 + 3.f * t11;
    float c12 =  3.f * t10 - 6.f * t11 + 3.f * t12;
    float c13 = -1.f * t10 + 3.f * t11 - 3.f * t12 + t13;

    const float2* sWbv = (const float2*)(sm + OFF_WB);
    const float2* sWxv = (const float2*)(sm + OFF_WX);
    const float2* sW1v = (const float2*)(sm + OFF_W1);
    const float*  sW2  = sm + OFF_W2;
    const float*  sW3  = sm + OFF_W3;
    const float2* svc  = (const float2*)(sm + OFF_VC);
    const float2* sbWb = (const float2*)(sm + OFF_BWB);
    const float2* sbWx = (const float2*)(sm + OFF_BWX);
    const float2* sb1  = (const float2*)(sm + OFF_B1);

    int lane = t & 31;
    int wid  = t >> 5;
    // per-warp stage: SH (h, later r), SP0 (p0, later y1), SP1 (p1)
    float* SH  = sm + W_SMEM_FLOATS + wid * 768;
    float* SP0 = SH + 256;
    float* SP1 = SH + 512;

    const float2* h2v = (const float2*)g_h;
    const float2* t1v = (const float2*)g_t1;
    const float2* t2v = (const float2*)g_t2;
    const float2* t3v = (const float2*)g_t3;

    int gw = (blockIdx.x * blockDim.x + t) >> 5;
    int nw = (gridDim.x * blockDim.x) >> 5;
    const int NG = NN / 4;   // 25000, exact

    for (int g = gw; g < NG; g += nw) {
        int n0 = g * 4;
        float2 p0r[4], p1r[4];
#pragma unroll
        for (int i = 0; i < 4; i++) {
            size_t base = (size_t)(n0 + i) * 32 + lane;
            float2 h  = __ldg(&h2v[base]);
            float2 x1 = __ldg(&t1v[base]);
            float2 x2 = __ldg(&t2v[base]);
            float2 x3 = __ldg(&t3v[base]);
            float2 p0, p1;
            p0.x = fmaf(c00, h.x, fmaf(c01, x1.x, fmaf(c02, x2.x, c03 * x3.x)));
            p0.y = fmaf(c00, h.y, fmaf(c01, x1.y, fmaf(c02, x2.y, c03 * x3.y)));
            p1.x = fmaf(c10, h.x, fmaf(c11, x1.x, fmaf(c12, x2.x, c13 * x3.x)));
            p1.y = fmaf(c10, h.y, fmaf(c11, x1.y, fmaf(c12, x2.y, c13 * x3.y)));
            p0r[i] = p0; p1r[i] = p1;
            *(float2*)&SH [i * 64 + 2 * lane] = h;
            *(float2*)&SP0[i * 64 + 2 * lane] = p0;
            *(float2*)&SP1[i * 64 + 2 * lane] = p1;
        }
        __syncwarp();

        // merged matvecs: pp0 = Wb^T p0, pp1 = Wb^T p1, xp = Wx^T h
        float2 pp0[4], pp1[4], xp[4];
        {
            float2 bb = sbWb[lane], bx = sbWx[lane];
#pragma unroll
            for (int i = 0; i < 4; i++) { pp0[i] = bb; pp1[i] = bb; xp[i] = bx; }
        }
        for (int k4 = 0; k4 < 16; k4++) {
            float vh[4][4], vp0[4][4], vp1[4][4];
#pragma unroll
            for (int i = 0; i < 4; i++) {
                *(float4*)vh[i]  = *(const float4*)&SH [i * 64 + k4 * 4];
                *(float4*)vp0[i] = *(const float4*)&SP0[i * 64 + k4 * 4];
                *(float4*)vp1[i] = *(const float4*)&SP1[i * 64 + k4 * 4];
            }
#pragma unroll
            for (int kk = 0; kk < 4; kk++) {
                int k = k4 * 4 + kk;
                float2 wb_ = sWbv[k * 32 + lane];
                float2 wx_ = sWxv[k * 32 + lane];
#pragma unroll
                for (int i = 0; i < 4; i++) {
                    pp0[i].x = fmaf(vp0[i][kk], wb_.x, pp0[i].x);
                    pp0[i].y = fmaf(vp0[i][kk], wb_.y, pp0[i].y);
                    pp1[i].x = fmaf(vp1[i][kk], wb_.x, pp1[i].x);
                    pp1[i].y = fmaf(vp1[i][kk], wb_.y, pp1[i].y);
                    xp[i].x  = fmaf(vh[i][kk],  wx_.x, xp[i].x);
                    xp[i].y  = fmaf(vh[i][kk],  wx_.y, xp[i].y);
                }
            }
        }
        __syncwarp();

        // attention + combine; stage r into SH
        float2 vcl = svc[lane];
#pragma unroll
        for (int i = 0; i < 4; i++) {
            float s0 = warpsum(tanh_fast(pp0[i].x + xp[i].x) * vcl.x +
                               tanh_fast(pp0[i].y + xp[i].y) * vcl.y);
            float s1 = warpsum(tanh_fast(pp1[i].x + xp[i].x) * vcl.x +
                               tanh_fast(pp1[i].y + xp[i].y) * vcl.y);
            float m = fmaxf(s0, s1);
            float e0 = __expf(s0 - m), e1 = __expf(s1 - m);
            float inv = 1.f / (e0 + e1);
            float a0 = e0 * inv, a1 = e1 * inv;
            float2 r;
            r.x = a0 * p0r[i].x + a1 * p1r[i].x;
            r.y = a0 * p0r[i].y + a1 * p1r[i].y;
            *(float2*)&SH[i * 64 + 2 * lane] = r;
        }
        __syncwarp();

        // y1 = relu(W1^T r + b1); stage y1 into SP0
        float2 y1[4];
        {
            float2 b = sb1[lane];
#pragma unroll
            for (int i = 0; i < 4; i++) y1[i] = b;
        }
        for (int k4 = 0; k4 < 16; k4++) {
            float vr[4][4];
#pragma unroll
            for (int i = 0; i < 4; i++)
                *(float4*)vr[i] = *(const float4*)&SH[i * 64 + k4 * 4];
#pragma unroll
            for (int kk = 0; kk < 4; kk++) {
                int k = k4 * 4 + kk;
                float2 w1_ = sW1v[k * 32 + lane];
#pragma unroll
                for (int i = 0; i < 4; i++) {
                    y1[i].x = fmaf(vr[i][kk], w1_.x, y1[i].x);
                    y1[i].y = fmaf(vr[i][kk], w1_.y, y1[i].y);
                }
            }
        }
        __syncwarp();
#pragma unroll
        for (int i = 0; i < 4; i++) {
            y1[i].x = fmaxf(y1[i].x, 0.f);
            y1[i].y = fmaxf(y1[i].y, 0.f);
            *(float2*)&SP0[i * 64 + 2 * lane] = y1[i];
        }
        __syncwarp();

        // y2[c]=relu(W2^T y1 + b2), c = lane (32 outputs)
        float acc[4];
        {
            float b = sm[OFF_B2 + lane];
#pragma unroll
            for (int i = 0; i < 4; i++) acc[i] = b;
        }
        for (int k4 = 0; k4 < 16; k4++) {
            float vy[4][4];
#pragma unroll
            for (int i = 0; i < 4; i++)
                *(float4*)vy[i] = *(const float4*)&SP0[i * 64 + k4 * 4];
#pragma unroll
            for (int kk = 0; kk < 4; kk++) {
                int k = k4 * 4 + kk;
                float w2_ = sW2[k * 32 + lane];
#pragma unroll
                for (int i = 0; i < 4; i++)
                    acc[i] = fmaf(vy[i][kk], w2_, acc[i]);
            }
        }

        float w30 = sW3[lane * 2 + 0];
        float w31 = sW3[lane * 2 + 1];
        float ob0 = sm[OFF_B3 + 0], ob1 = sm[OFF_B3 + 1];
#pragma unroll
        for (int i = 0; i < 4; i++) {
            float y2 = fmaxf(acc[i], 0.f);
            float q0 = warpsum(y2 * w30);
            float q1 = warpsum(y2 * w31);
            if (lane == 0) {
                out[(size_t)(n0 + i) * 2 + 0] = ob0 + q0;
                out[(size_t)(n0 + i) * 2 + 1] = ob1 + q1;
            }
        }
    }
}

// ---------------- launch ----------------------------------------------------
extern "C" void kernel_launch(void* const* d_in, const int* in_sizes, int n_in,
                              void* d_out, int out_size) {
    const float* x      = (const float*)d_in[0];
    const void*  esrc   = d_in[1];
    const void*  edst   = d_in[2];
    const float* evals  = (const float*)d_in[3];
    const float* Win    = (const float*)d_in[4];
    const float* bin    = (const float*)d_in[5];
    const float* thetas = (const float*)d_in[6];
    const float* Wb     = (const float*)d_in[7];
    const float* bWb    = (const float*)d_in[8];
    const float* Wx     = (const float*)d_in[9];
    const float* bWx    = (const float*)d_in[10];
    const float* vc     = (const float*)d_in[11];
    const float* W1     = (const float*)d_in[12];
    const float* b1     = (const float*)d_in[13];
    const float* W2     = (const float*)d_in[14];
    const float* b2     = (const float*)d_in[15];
    const float* W3     = (const float*)d_in[16];
    const float* b3     = (const float*)d_in[17];
    float* out = (float*)d_out;

    // one-time resources (host-side only; no device memory)
    static cudaStream_t s2 = nullptr;
    static cudaEvent_t evFork = nullptr, evJoin = nullptr;
    if (s2 == nullptr) {
        cudaStreamCreateWithFlags(&s2, cudaStreamNonBlocking);
        cudaEventCreateWithFlags(&evFork, cudaEventDisableTiming);
        cudaEventCreateWithFlags(&evJoin, cudaEventDisableTiming);
        cudaFuncSetAttribute(epilogue_kernel,
                             cudaFuncAttributeMaxDynamicSharedMemorySize,
                             EPI_SMEM_BYTES);
    }

    // fork: CSR build on s2, gemm_in on the main (capture) stream
    cudaEventRecord(evFork, 0);
    cudaStreamWaitEvent(s2, evFork, 0);

    detect_kernel<<<1, 32, 0, s2>>>((const unsigned int*)esrc);
    zero_cnt_kernel<<<(NN + 255) / 256, 256, 0, s2>>>();
    convert_hist_kernel<<<(EE + 255) / 256, 256, 0, s2>>>(esrc, edst);
    scan_block_kernel<<<NB_SCAN, 512, 0, s2>>>();
    scan_bsum_kernel<<<1, 256, 0, s2>>>();
    add_offsets_kernel<<<(NN + 255) / 256, 256, 0, s2>>>();
    scatter_kernel<<<(EE + 255) / 256, 256, 0, s2>>>(evals);
    cudaEventRecord(evJoin, s2);

    gemm_in_kernel<<<1184, 256>>>(x, Win, bin);

    // join: SpMM needs both h and the CSR structure
    cudaStreamWaitEvent(0, evJoin, 0);

    spmm_csr_kernel<0><<<1184, 256>>>();
    spmm_csr_kernel<1><<<1184, 256>>>();
    spmm_csr_kernel<2><<<1184, 256>>>();

    epilogue_kernel<<<296, 256, EPI_SMEM_BYTES>>>(
        thetas, Wb, bWb, Wx, bWx, vc, W1, b1, W2, b2, W3, b3, out);
}